// round 1
// baseline (speedup 1.0000x reference)
#include <cuda_runtime.h>
#include <math.h>

// ---------------- problem constants ----------------
constexpr int Nn  = 50000;     // nodes
constexpr int Ne  = 800000;    // edges (without self loops)
constexpr int NeT = 850000;    // edges + self loops
constexpr int Bb  = 256;       // graphs / batch
constexpr int Tt  = 50;        // timesteps
constexpr int DIM = 128;       // feature dim (H*C1 == C2 == 128)
constexpr int HEADS = 4;
constexpr int LH  = 128;       // lstm hidden
constexpr int QD  = 32;        // lstm input dim

// ---------------- device scratch ----------------
__device__ float    d_xw[Nn * DIM];        // x @ gat_W
__device__ float    d_asrc[Nn * HEADS];
__device__ float    d_adst[Nn * HEADS];
__device__ float    d_escr[NeT * HEADS];   // e then ex per edge
__device__ unsigned d_menc[Nn * HEADS];    // encoded segment max
__device__ float    d_ssum[Nn * HEADS];    // segment exp-sum
__device__ float    d_deg[Nn];
__device__ float    d_hacc[Nn * DIM];      // GAT aggregation
__device__ float    d_h[Nn * DIM];         // post elu+bn1
__device__ float    d_dinv[Nn];
__device__ float    d_hw[Nn * DIM];        // h @ gcn_W
__device__ float    d_h2acc[Nn * DIM];     // GCN aggregation
__device__ float    d_h2[Nn * DIM];        // post elu+bn2
__device__ float    d_gate[Nn];
__device__ unsigned d_gmenc[Bb];
__device__ float    d_gs[Bb];
__device__ float    d_gex[Nn];
__device__ float    d_grep[Bb * DIM];
__device__ float    d_xpre[Tt * 4 * LH * Bb];  // [t][gate*128+u][b]
__device__ float    d_hl0[LH * Bb];            // [u][b]
__device__ float    d_hl1[LH * Bb];
__device__ float    d_cl[LH * Bb];

// ---------------- helpers ----------------
__device__ __forceinline__ unsigned fenc(float f) {
    unsigned b = __float_as_uint(f);
    return (b & 0x80000000u) ? ~b : (b | 0x80000000u);
}
__device__ __forceinline__ float fdec(unsigned e) {
    unsigned b = (e & 0x80000000u) ? (e ^ 0x80000000u) : ~e;
    return __uint_as_float(b);
}
__device__ __forceinline__ float sigf(float x) { return 1.0f / (1.0f + __expf(-x)); }

// ---------------- init (zero accumulators) ----------------
__global__ void k_init() {
    int stride = gridDim.x * blockDim.x;
    for (int i = blockIdx.x * blockDim.x + threadIdx.x; i < Nn * DIM; i += stride) {
        d_hacc[i] = 0.f;
        d_h2acc[i] = 0.f;
        if (i < Nn * HEADS) { d_ssum[i] = 0.f; d_menc[i] = 0u; }
        if (i < Nn) d_deg[i] = 0.f;
        if (i < Bb * DIM) { d_grep[i] = 0.f; d_hl0[i] = 0.f; d_cl[i] = 0.f; }
        if (i < Bb) { d_gs[i] = 0.f; d_gmenc[i] = 0u; }
    }
}

// ---------------- GAT gemm: xw = x @ gat_W, plus per-head attention dots ----------------
__global__ void k_gat_gemm(const float* __restrict__ x, const float* __restrict__ W,
                           const float* __restrict__ att_s, const float* __restrict__ att_d) {
    __shared__ float sx[4][DIM];
    int w = threadIdx.x >> 5, lane = threadIdx.x & 31;
    int row = blockIdx.x * 4 + w;
    float4 xv = reinterpret_cast<const float4*>(x + row * DIM)[lane];
    reinterpret_cast<float4*>(sx[w])[lane] = xv;
    __syncwarp();
    const float4* W4 = reinterpret_cast<const float4*>(W);
    float4 acc = make_float4(0.f, 0.f, 0.f, 0.f);
#pragma unroll 8
    for (int k = 0; k < DIM; k++) {
        float xk = sx[w][k];
        float4 wv = W4[k * 32 + lane];
        acc.x += xk * wv.x; acc.y += xk * wv.y; acc.z += xk * wv.z; acc.w += xk * wv.w;
    }
    reinterpret_cast<float4*>(d_xw + row * DIM)[lane] = acc;
    int c0 = lane * 4;
    float ps = acc.x * att_s[c0] + acc.y * att_s[c0 + 1] + acc.z * att_s[c0 + 2] + acc.w * att_s[c0 + 3];
    float pd = acc.x * att_d[c0] + acc.y * att_d[c0 + 1] + acc.z * att_d[c0 + 2] + acc.w * att_d[c0 + 3];
#pragma unroll
    for (int off = 4; off; off >>= 1) {
        ps += __shfl_xor_sync(0xffffffffu, ps, off);
        pd += __shfl_xor_sync(0xffffffffu, pd, off);
    }
    if ((lane & 7) == 0) {
        int h = lane >> 3;
        d_asrc[row * HEADS + h] = ps;
        d_adst[row * HEADS + h] = pd;
    }
}

// ---------------- edge pass 1: e = leaky_relu(asrc[src]+adst[dst]); seg max; deg ----------------
__global__ void k_edge1(const int* __restrict__ ei) {
    int e = blockIdx.x * blockDim.x + threadIdx.x;
    if (e >= NeT) return;
    int s, d;
    if (e < Ne) { s = ei[e]; d = ei[Ne + e]; } else { s = d = e - Ne; }
    float4 as = *reinterpret_cast<const float4*>(d_asrc + s * 4);
    float4 ad = *reinterpret_cast<const float4*>(d_adst + d * 4);
    float4 v;
    v.x = as.x + ad.x; v.y = as.y + ad.y; v.z = as.z + ad.z; v.w = as.w + ad.w;
    v.x = v.x > 0.f ? v.x : 0.2f * v.x;
    v.y = v.y > 0.f ? v.y : 0.2f * v.y;
    v.z = v.z > 0.f ? v.z : 0.2f * v.z;
    v.w = v.w > 0.f ? v.w : 0.2f * v.w;
    *reinterpret_cast<float4*>(d_escr + e * 4) = v;
    atomicMax(&d_menc[d * 4 + 0], fenc(v.x));
    atomicMax(&d_menc[d * 4 + 1], fenc(v.y));
    atomicMax(&d_menc[d * 4 + 2], fenc(v.z));
    atomicMax(&d_menc[d * 4 + 3], fenc(v.w));
    atomicAdd(&d_deg[d], 1.0f);
}

// ---------------- edge pass 2: ex = exp(e - m[dst]); seg sum ----------------
__global__ void k_edge2(const int* __restrict__ ei) {
    int e = blockIdx.x * blockDim.x + threadIdx.x;
    if (e >= NeT) return;
    int d;
    if (e < Ne) { d = ei[Ne + e]; } else { d = e - Ne; }
    float4 v = *reinterpret_cast<const float4*>(d_escr + e * 4);
    uint4 me = *reinterpret_cast<const uint4*>(d_menc + d * 4);
    float4 ex;
    ex.x = __expf(v.x - fdec(me.x));
    ex.y = __expf(v.y - fdec(me.y));
    ex.z = __expf(v.z - fdec(me.z));
    ex.w = __expf(v.w - fdec(me.w));
    *reinterpret_cast<float4*>(d_escr + e * 4) = ex;
    atomicAdd(&d_ssum[d * 4 + 0], ex.x);
    atomicAdd(&d_ssum[d * 4 + 1], ex.y);
    atomicAdd(&d_ssum[d * 4 + 2], ex.z);
    atomicAdd(&d_ssum[d * 4 + 3], ex.w);
}

// ---------------- edge pass 3: hacc[dst] += xw[src] * alpha (warp per edge) ----------------
__global__ void k_edge3(const int* __restrict__ ei) {
    int gt = blockIdx.x * blockDim.x + threadIdx.x;
    int e = gt >> 5, lane = gt & 31;
    if (e >= NeT) return;
    int s, d;
    if (e < Ne) { s = ei[e]; d = ei[Ne + e]; } else { s = d = e - Ne; }
    float4 ex = *reinterpret_cast<const float4*>(d_escr + e * 4);
    float4 sm = *reinterpret_cast<const float4*>(d_ssum + d * 4);
    float a0 = ex.x / (sm.x + 1e-16f);
    float a1 = ex.y / (sm.y + 1e-16f);
    float a2 = ex.z / (sm.z + 1e-16f);
    float a3 = ex.w / (sm.w + 1e-16f);
    const float* xs = d_xw + s * DIM;
    float* hb = d_hacc + d * DIM;
    atomicAdd(hb + lane,      xs[lane]      * a0);
    atomicAdd(hb + lane + 32, xs[lane + 32] * a1);
    atomicAdd(hb + lane + 64, xs[lane + 64] * a2);
    atomicAdd(hb + lane + 96, xs[lane + 96] * a3);
}

// ---------------- node A: h = bn1(elu(hacc + gat_b)) ----------------
__global__ void k_nodeA(const float* __restrict__ gat_b, const float* __restrict__ g1,
                        const float* __restrict__ b1, const float* __restrict__ m1,
                        const float* __restrict__ v1) {
    int stride = gridDim.x * blockDim.x;
    for (int i = blockIdx.x * blockDim.x + threadIdx.x; i < Nn * DIM; i += stride) {
        int c = i & (DIM - 1);
        float v = d_hacc[i] + gat_b[c];
        v = v > 0.f ? v : (__expf(v) - 1.0f);
        v = g1[c] * (v - m1[c]) * rsqrtf(v1[c] + 1e-5f) + b1[c];
        d_h[i] = v;
    }
}

__global__ void k_dinv() {
    int i = blockIdx.x * blockDim.x + threadIdx.x;
    if (i >= Nn) return;
    float dg = d_deg[i];
    d_dinv[i] = dg > 0.f ? rsqrtf(dg) : 0.f;
}

// ---------------- GCN gemm: hw = h @ gcn_W ----------------
__global__ void k_gcn_gemm(const float* __restrict__ W) {
    __shared__ float sx[4][DIM];
    int w = threadIdx.x >> 5, lane = threadIdx.x & 31;
    int row = blockIdx.x * 4 + w;
    float4 xv = reinterpret_cast<const float4*>(d_h + row * DIM)[lane];
    reinterpret_cast<float4*>(sx[w])[lane] = xv;
    __syncwarp();
    const float4* W4 = reinterpret_cast<const float4*>(W);
    float4 acc = make_float4(0.f, 0.f, 0.f, 0.f);
#pragma unroll 8
    for (int k = 0; k < DIM; k++) {
        float xk = sx[w][k];
        float4 wv = W4[k * 32 + lane];
        acc.x += xk * wv.x; acc.y += xk * wv.y; acc.z += xk * wv.z; acc.w += xk * wv.w;
    }
    reinterpret_cast<float4*>(d_hw + row * DIM)[lane] = acc;
}

// ---------------- edge pass 4: h2acc[dst] += hw[src] * norm (warp per edge) ----------------
__global__ void k_edge4(const int* __restrict__ ei) {
    int gt = blockIdx.x * blockDim.x + threadIdx.x;
    int e = gt >> 5, lane = gt & 31;
    if (e >= NeT) return;
    int s, d;
    if (e < Ne) { s = ei[e]; d = ei[Ne + e]; } else { s = d = e - Ne; }
    float norm = d_dinv[s] * d_dinv[d];
    const float* xs = d_hw + s * DIM;
    float* hb = d_h2acc + d * DIM;
    atomicAdd(hb + lane,      xs[lane]      * norm);
    atomicAdd(hb + lane + 32, xs[lane + 32] * norm);
    atomicAdd(hb + lane + 64, xs[lane + 64] * norm);
    atomicAdd(hb + lane + 96, xs[lane + 96] * norm);
}

// ---------------- node B: h2 = bn2(elu(h2acc + gcn_b)); gate; seg max over batch ----------------
__global__ void k_nodeB(const float* __restrict__ gcn_b, const float* __restrict__ g2,
                        const float* __restrict__ b2, const float* __restrict__ m2,
                        const float* __restrict__ v2, const float* __restrict__ gateW,
                        const float* __restrict__ gate_b, const int* __restrict__ batch) {
    __shared__ float sred[4];
    int n = blockIdx.x;
    int c = threadIdx.x;
    int lane = c & 31, wid = c >> 5;
    float v = d_h2acc[n * DIM + c] + gcn_b[c];
    v = v > 0.f ? v : (__expf(v) - 1.0f);
    v = g2[c] * (v - m2[c]) * rsqrtf(v2[c] + 1e-5f) + b2[c];
    d_h2[n * DIM + c] = v;
    float p = v * gateW[c];
#pragma unroll
    for (int off = 16; off; off >>= 1) p += __shfl_xor_sync(0xffffffffu, p, off);
    if (lane == 0) sred[wid] = p;
    __syncthreads();
    if (c == 0) {
        float g = sred[0] + sred[1] + sred[2] + sred[3] + gate_b[0];
        d_gate[n] = g;
        atomicMax(&d_gmenc[batch[n]], fenc(g));
    }
}

// ---------------- pooling softmax passes ----------------
__global__ void k_poolex(const int* __restrict__ batch) {
    int n = blockIdx.x * blockDim.x + threadIdx.x;
    if (n >= Nn) return;
    int bt = batch[n];
    float ex = __expf(d_gate[n] - fdec(d_gmenc[bt]));
    d_gex[n] = ex;
    atomicAdd(&d_gs[bt], ex);
}

__global__ void k_poolsum(const int* __restrict__ batch) {
    int gt = blockIdx.x * blockDim.x + threadIdx.x;
    int n = gt >> 5, lane = gt & 31;
    if (n >= Nn) return;
    int bt = batch[n];
    float sc = d_gex[n] / (d_gs[bt] + 1e-16f);
    const float* hr = d_h2 + n * DIM;
    float* gr = d_grep + bt * DIM;
    atomicAdd(gr + lane,      sc * hr[lane]);
    atomicAdd(gr + lane + 32, sc * hr[lane + 32]);
    atomicAdd(gr + lane + 64, sc * hr[lane + 64]);
    atomicAdd(gr + lane + 96, sc * hr[lane + 96]);
}

// ---------------- LSTM input projection: xpre[t][j][b] = quant[b,t,:] @ Wih[j,:] + bih[j]+bhh[j] ----------------
__global__ void k_xpre(const float* __restrict__ quant, const float* __restrict__ Wih,
                       const float* __restrict__ bih, const float* __restrict__ bhh) {
    __shared__ float4 sq[32][8];
    int t = blockIdx.x;
    int bbase = blockIdx.y * 32;
    int tid = threadIdx.x;  // 512
    for (int i = tid; i < 32 * 8; i += 512) {
        int b = i >> 3, k = i & 7;
        sq[b][k] = reinterpret_cast<const float4*>(quant + ((size_t)(bbase + b) * Tt + t) * QD)[k];
    }
    __syncthreads();
    int j = tid;
    float wr[QD];
#pragma unroll
    for (int k = 0; k < QD; k++) wr[k] = Wih[j * QD + k];
    float bs = bih[j] + bhh[j];
    float* outp = d_xpre + ((size_t)t * 512 + j) * Bb + bbase;
    for (int b = 0; b < 32; b++) {
        float acc = bs;
#pragma unroll
        for (int k8 = 0; k8 < 8; k8++) {
            float4 q = sq[b][k8];
            acc += q.x * wr[k8 * 4] + q.y * wr[k8 * 4 + 1] + q.z * wr[k8 * 4 + 2] + q.w * wr[k8 * 4 + 3];
        }
        outp[b] = acc;
    }
}

// ---------------- LSTM step ----------------
__global__ __launch_bounds__(256) void k_lstm_step(const float* __restrict__ Whh, int t) {
    __shared__ float sh[LH][33];
    __shared__ float sW[4][8][LH];
    const float* hprev = (t & 1) ? d_hl1 : d_hl0;
    float* hnew = (t & 1) ? d_hl0 : d_hl1;
    int ugrp = blockIdx.x & 15, bgrp = blockIdx.x >> 4;
    int ubase = ugrp * 8, bbase = bgrp * 32;
    int tid = threadIdx.x;  // 256
    for (int i = tid; i < LH * 32; i += 256) {
        int k = i >> 5, bl = i & 31;
        sh[k][bl] = hprev[k * Bb + bbase + bl];
    }
    for (int i = tid; i < 32 * LH; i += 256) {
        int rl = i >> 7, k = i & 127;
        int g = rl >> 3, uu = rl & 7;
        sW[g][uu][k] = Whh[(g * LH + ubase + uu) * LH + k];
    }
    __syncthreads();
    int uu = tid >> 5, bl = tid & 31;
    int u = ubase + uu, b = bbase + bl;
    const float* xp = d_xpre + (size_t)t * 512 * Bb;
    float a0 = xp[(0 * LH + u) * Bb + b];
    float a1 = xp[(1 * LH + u) * Bb + b];
    float a2 = xp[(2 * LH + u) * Bb + b];
    float a3 = xp[(3 * LH + u) * Bb + b];
#pragma unroll 4
    for (int k = 0; k < LH; k++) {
        float hv = sh[k][bl];
        a0 += hv * sW[0][uu][k];
        a1 += hv * sW[1][uu][k];
        a2 += hv * sW[2][uu][k];
        a3 += hv * sW[3][uu][k];
    }
    float iv = sigf(a0);
    float fv = sigf(a1);
    float gv = tanhf(a2);
    float ov = sigf(a3);
    int ci = u * Bb + b;
    float cc = fv * d_cl[ci] + iv * gv;
    d_cl[ci] = cc;
    hnew[ci] = ov * tanhf(cc);
}

// ---------------- final linear ----------------
__global__ void k_final(const float* __restrict__ fcW, const float* __restrict__ fcb,
                        float* __restrict__ out) {
    int b = threadIdx.x;  // 256
    const float* hT = d_hl0;  // t=49 (odd) writes into d_hl0
    float acc = fcb[0];
#pragma unroll 4
    for (int c = 0; c < DIM; c++) acc += d_grep[b * DIM + c] * fcW[c];
#pragma unroll 4
    for (int u = 0; u < LH; u++) acc += hT[u * Bb + b] * fcW[DIM + u];
    out[b] = acc;
}

// ---------------- launch ----------------
extern "C" void kernel_launch(void* const* d_in, const int* in_sizes, int n_in,
                              void* d_out, int out_size) {
    (void)in_sizes; (void)n_in; (void)out_size;
    const float* x       = (const float*)d_in[0];
    const int*   ei      = (const int*)d_in[1];
    const int*   batch   = (const int*)d_in[2];
    const float* quant   = (const float*)d_in[3];
    const float* gat_W   = (const float*)d_in[4];
    const float* att_src = (const float*)d_in[5];
    const float* att_dst = (const float*)d_in[6];
    const float* gat_b   = (const float*)d_in[7];
    const float* bn1_g   = (const float*)d_in[8];
    const float* bn1_b   = (const float*)d_in[9];
    const float* bn1_m   = (const float*)d_in[10];
    const float* bn1_v   = (const float*)d_in[11];
    const float* gcn_W   = (const float*)d_in[12];
    const float* gcn_b   = (const float*)d_in[13];
    const float* bn2_g   = (const float*)d_in[14];
    const float* bn2_b   = (const float*)d_in[15];
    const float* bn2_m   = (const float*)d_in[16];
    const float* bn2_v   = (const float*)d_in[17];
    const float* gate_W  = (const float*)d_in[18];
    const float* gate_b  = (const float*)d_in[19];
    const float* Wih     = (const float*)d_in[20];
    const float* Whh     = (const float*)d_in[21];
    const float* bih     = (const float*)d_in[22];
    const float* bhh     = (const float*)d_in[23];
    const float* fcW     = (const float*)d_in[24];
    const float* fcb     = (const float*)d_in[25];
    float* out = (float*)d_out;

    k_init<<<4096, 256>>>();
    k_gat_gemm<<<Nn / 4, 128>>>(x, gat_W, att_src, att_dst);
    k_edge1<<<(NeT + 255) / 256, 256>>>(ei);
    k_edge2<<<(NeT + 255) / 256, 256>>>(ei);
    k_edge3<<<(NeT * 32 + 255) / 256, 256>>>(ei);
    k_nodeA<<<8192, 256>>>(gat_b, bn1_g, bn1_b, bn1_m, bn1_v);
    k_dinv<<<(Nn + 255) / 256, 256>>>();
    k_gcn_gemm<<<Nn / 4, 128>>>(gcn_W);
    k_edge4<<<(NeT * 32 + 255) / 256, 256>>>(ei);
    k_nodeB<<<Nn, 128>>>(gcn_b, bn2_g, bn2_b, bn2_m, bn2_v, gate_W, gate_b, batch);
    k_poolex<<<(Nn + 255) / 256, 256>>>(batch);
    k_poolsum<<<(Nn * 32 + 255) / 256, 256>>>(batch);
    k_xpre<<<dim3(Tt, Bb / 32), 512>>>(quant, Wih, bih, bhh);
    for (int t = 0; t < Tt; t++) {
        k_lstm_step<<<128, 256>>>(Whh, t);
    }
    k_final<<<1, 256>>>(fcW, fcb, out);
}

// round 2
// speedup vs baseline: 1.3875x; 1.3875x over previous
#include <cuda_runtime.h>
#include <math.h>

// ---------------- problem constants ----------------
constexpr int Nn  = 50000;     // nodes
constexpr int Ne  = 800000;    // edges (without self loops)
constexpr int NeT = 850000;    // edges + self loops
constexpr int Bb  = 256;       // graphs / batch
constexpr int Tt  = 50;        // timesteps
constexpr int DIM = 128;       // feature dim (H*C1 == C2 == 128)
constexpr int LH  = 128;       // lstm hidden
constexpr int QD  = 32;        // lstm input dim
constexpr int CAP = 64;        // per-row smem edge cache (deg ~ Poisson(17))
constexpr int SCAN_B = (Nn + 511) / 512;   // 98

// ---------------- device scratch ----------------
__device__ float    d_xw[Nn * DIM];        // x @ gat_W
__device__ float    d_asrc[Nn * 4];
__device__ float    d_adst[Nn * 4];
__device__ int      d_degi[Nn];
__device__ int      d_cnt[Nn];
__device__ int      d_off[Nn + 1];
__device__ int      d_bsum[SCAN_B];
__device__ int      d_bsx[SCAN_B];
__device__ int      d_srcs[NeT];           // CSR src per slot
__device__ float    d_escr[NeT * 4];       // raw leaky-relu scores, CSR order
__device__ float    d_h[Nn * DIM];         // post elu+bn1
__device__ float    d_dinv[Nn];
__device__ float    d_hw[Nn * DIM];        // h @ gcn_W
__device__ float    d_h2[Nn * DIM];        // post elu+bn2
__device__ float    d_gate[Nn];
__device__ float    d_grep[Bb * DIM];
__device__ float    d_xpre[Tt * 4 * LH * Bb];  // [t][gate*128+u][b]
__device__ float    d_hl0[LH * Bb];            // [u][b]
__device__ float    d_hl1[LH * Bb];
__device__ float    d_cl[LH * Bb];

__device__ __forceinline__ float sigf(float x) { return 1.0f / (1.0f + __expf(-x)); }

// ---------------- init ----------------
__global__ void k_init() {
    int stride = gridDim.x * blockDim.x;
    for (int i = blockIdx.x * blockDim.x + threadIdx.x; i < Nn; i += stride) {
        d_degi[i] = 0;
        d_cnt[i]  = 0;
        if (i < LH * Bb) { d_hl0[i] = 0.f; d_cl[i] = 0.f; }
    }
}

// ---------------- GAT gemm: xw = x @ gat_W, 2 rows/warp, + per-head att dots ----------------
__global__ void k_gat_gemm(const float* __restrict__ x, const float* __restrict__ W,
                           const float* __restrict__ att_s, const float* __restrict__ att_d) {
    __shared__ float sx[8][DIM];
    int w = threadIdx.x >> 5, lane = threadIdx.x & 31;
    int r0 = blockIdx.x * 8 + w * 2;
    reinterpret_cast<float4*>(sx[w * 2])[lane]     = reinterpret_cast<const float4*>(x + (size_t)r0 * DIM)[lane];
    reinterpret_cast<float4*>(sx[w * 2 + 1])[lane] = reinterpret_cast<const float4*>(x + (size_t)(r0 + 1) * DIM)[lane];
    __syncwarp();
    const float4* W4 = reinterpret_cast<const float4*>(W);
    float4 aA = make_float4(0.f, 0.f, 0.f, 0.f);
    float4 aB = make_float4(0.f, 0.f, 0.f, 0.f);
#pragma unroll 4
    for (int k = 0; k < DIM; k++) {
        float4 wv = W4[k * 32 + lane];
        float xa = sx[w * 2][k], xb = sx[w * 2 + 1][k];
        aA.x += xa * wv.x; aA.y += xa * wv.y; aA.z += xa * wv.z; aA.w += xa * wv.w;
        aB.x += xb * wv.x; aB.y += xb * wv.y; aB.z += xb * wv.z; aB.w += xb * wv.w;
    }
    reinterpret_cast<float4*>(d_xw + (size_t)r0 * DIM)[lane]       = aA;
    reinterpret_cast<float4*>(d_xw + (size_t)(r0 + 1) * DIM)[lane] = aB;
    int c0 = lane * 4;
    float s0 = att_s[c0], s1 = att_s[c0 + 1], s2 = att_s[c0 + 2], s3 = att_s[c0 + 3];
    float d0 = att_d[c0], d1 = att_d[c0 + 1], d2 = att_d[c0 + 2], d3 = att_d[c0 + 3];
#pragma unroll
    for (int r = 0; r < 2; r++) {
        float4 a = r ? aB : aA;
        float ps = a.x * s0 + a.y * s1 + a.z * s2 + a.w * s3;
        float pd = a.x * d0 + a.y * d1 + a.z * d2 + a.w * d3;
#pragma unroll
        for (int off = 4; off; off >>= 1) {
            ps += __shfl_xor_sync(0xffffffffu, ps, off);
            pd += __shfl_xor_sync(0xffffffffu, pd, off);
        }
        if ((lane & 7) == 0) {
            int h = lane >> 3;
            d_asrc[(r0 + r) * 4 + h] = ps;
            d_adst[(r0 + r) * 4 + h] = pd;
        }
    }
}

// ---------------- CSR build ----------------
__global__ void k_count(const int* __restrict__ ei) {
    int e = blockIdx.x * blockDim.x + threadIdx.x;
    if (e >= NeT) return;
    int d = (e < Ne) ? ei[Ne + e] : e - Ne;
    atomicAdd(&d_degi[d], 1);
}

__global__ void k_scan1() {
    __shared__ int wsum[16];
    int i = blockIdx.x * 512 + threadIdx.x;
    int v = (i < Nn) ? d_degi[i] : 0;
    int lane = threadIdx.x & 31, wid = threadIdx.x >> 5;
    int inc = v;
#pragma unroll
    for (int o = 1; o < 32; o <<= 1) {
        int t = __shfl_up_sync(0xffffffffu, inc, o);
        if (lane >= o) inc += t;
    }
    if (lane == 31) wsum[wid] = inc;
    __syncthreads();
    if (wid == 0) {
        int wv = (lane < 16) ? wsum[lane] : 0;
#pragma unroll
        for (int o = 1; o < 16; o <<= 1) {
            int t = __shfl_up_sync(0xffffffffu, wv, o);
            if (lane >= o) wv += t;
        }
        if (lane < 16) wsum[lane] = wv;
    }
    __syncthreads();
    int woff = (wid > 0) ? wsum[wid - 1] : 0;
    if (i < Nn) d_off[i] = woff + inc - v;
    if (threadIdx.x == 0) d_bsum[blockIdx.x] = wsum[15];
}

__global__ void k_scan2() {
    if (threadIdx.x != 0 || blockIdx.x != 0) return;
    int run = 0;
    for (int i = 0; i < SCAN_B; i++) { int t = d_bsum[i]; d_bsx[i] = run; run += t; }
}

__global__ void k_scan3() {
    int i = blockIdx.x * 512 + threadIdx.x;
    if (i < Nn) d_off[i] += d_bsx[blockIdx.x];
    if (i == 0) d_off[Nn] = NeT;
}

__global__ void k_scatter(const int* __restrict__ ei) {
    int e = blockIdx.x * blockDim.x + threadIdx.x;
    if (e >= NeT) return;
    int s, d;
    if (e < Ne) { s = ei[e]; d = ei[Ne + e]; } else { s = d = e - Ne; }
    float4 as = *reinterpret_cast<const float4*>(d_asrc + s * 4);
    float4 ad = *reinterpret_cast<const float4*>(d_adst + d * 4);
    float4 v;
    v.x = as.x + ad.x; v.y = as.y + ad.y; v.z = as.z + ad.z; v.w = as.w + ad.w;
    v.x = v.x > 0.f ? v.x : 0.2f * v.x;
    v.y = v.y > 0.f ? v.y : 0.2f * v.y;
    v.z = v.z > 0.f ? v.z : 0.2f * v.z;
    v.w = v.w > 0.f ? v.w : 0.2f * v.w;
    int pos = d_off[d] + atomicAdd(&d_cnt[d], 1);
    d_srcs[pos] = s;
    *reinterpret_cast<float4*>(d_escr + (size_t)pos * 4) = v;
}

// ---------------- gather3: per-dst softmax + aggregate + bias/elu/bn1 + dinv ----------------
__global__ __launch_bounds__(256) void k_gather3(const float* __restrict__ gat_b,
                                                 const float* __restrict__ g1, const float* __restrict__ b1,
                                                 const float* __restrict__ m1, const float* __restrict__ v1) {
    __shared__ float sex[8][CAP * 4];
    int w = threadIdx.x >> 5, lane = threadIdx.x & 31;
    int n = blockIdx.x * 8 + w;
    if (n >= Nn) return;
    int row = d_off[n], end = d_off[n + 1], len = end - row;

    // phase A1: row max per head (and cache raw scores)
    float m0 = -1e30f, m1v = -1e30f, m2v = -1e30f, m3v = -1e30f;
    for (int base = 0; base < len; base += 32) {
        int j = base + lane;
        if (j < len) {
            float4 v = *reinterpret_cast<const float4*>(d_escr + (size_t)(row + j) * 4);
            if (j < CAP) *reinterpret_cast<float4*>(&sex[w][j * 4]) = v;
            m0 = fmaxf(m0, v.x); m1v = fmaxf(m1v, v.y); m2v = fmaxf(m2v, v.z); m3v = fmaxf(m3v, v.w);
        }
    }
#pragma unroll
    for (int o = 16; o; o >>= 1) {
        m0  = fmaxf(m0,  __shfl_xor_sync(0xffffffffu, m0,  o));
        m1v = fmaxf(m1v, __shfl_xor_sync(0xffffffffu, m1v, o));
        m2v = fmaxf(m2v, __shfl_xor_sync(0xffffffffu, m2v, o));
        m3v = fmaxf(m3v, __shfl_xor_sync(0xffffffffu, m3v, o));
    }
    // phase A2: exp + sum
    float s0 = 0.f, s1 = 0.f, s2 = 0.f, s3 = 0.f;
    for (int base = 0; base < len; base += 32) {
        int j = base + lane;
        if (j < len) {
            float4 v;
            if (j < CAP) v = *reinterpret_cast<float4*>(&sex[w][j * 4]);
            else         v = *reinterpret_cast<const float4*>(d_escr + (size_t)(row + j) * 4);
            v.x = __expf(v.x - m0);  v.y = __expf(v.y - m1v);
            v.z = __expf(v.z - m2v); v.w = __expf(v.w - m3v);
            if (j < CAP) *reinterpret_cast<float4*>(&sex[w][j * 4]) = v;
            s0 += v.x; s1 += v.y; s2 += v.z; s3 += v.w;
        }
    }
#pragma unroll
    for (int o = 16; o; o >>= 1) {
        s0 += __shfl_xor_sync(0xffffffffu, s0, o);
        s1 += __shfl_xor_sync(0xffffffffu, s1, o);
        s2 += __shfl_xor_sync(0xffffffffu, s2, o);
        s3 += __shfl_xor_sync(0xffffffffu, s3, o);
    }
    float r0 = 1.0f / (s0 + 1e-16f), r1 = 1.0f / (s1 + 1e-16f);
    float r2 = 1.0f / (s2 + 1e-16f), r3 = 1.0f / (s3 + 1e-16f);

    __syncwarp();
    // phase B: gather-aggregate
    float a0 = 0.f, a1 = 0.f, a2 = 0.f, a3 = 0.f;
    for (int j = 0; j < len; j++) {
        int sI = d_srcs[row + j];
        float w0, w1, w2, w3;
        if (j < CAP) {
            w0 = sex[w][j * 4 + 0] * r0; w1 = sex[w][j * 4 + 1] * r1;
            w2 = sex[w][j * 4 + 2] * r2; w3 = sex[w][j * 4 + 3] * r3;
        } else {
            float4 v = *reinterpret_cast<const float4*>(d_escr + (size_t)(row + j) * 4);
            w0 = __expf(v.x - m0)  * r0; w1 = __expf(v.y - m1v) * r1;
            w2 = __expf(v.z - m2v) * r2; w3 = __expf(v.w - m3v) * r3;
        }
        const float* xs = d_xw + (size_t)sI * DIM;
        a0 += xs[lane]      * w0;
        a1 += xs[lane + 32] * w1;
        a2 += xs[lane + 64] * w2;
        a3 += xs[lane + 96] * w3;
    }
    // phase C: bias + elu + bn1
    float acc[4] = {a0, a1, a2, a3};
#pragma unroll
    for (int hd = 0; hd < 4; hd++) {
        int c = lane + 32 * hd;
        float v = acc[hd] + gat_b[c];
        v = v > 0.f ? v : (__expf(v) - 1.0f);
        v = g1[c] * (v - m1[c]) * rsqrtf(v1[c] + 1e-5f) + b1[c];
        d_h[(size_t)n * DIM + c] = v;
    }
    if (lane == 0) d_dinv[n] = rsqrtf((float)len);
}

// ---------------- GCN gemm: hw = h @ gcn_W (2 rows/warp) ----------------
__global__ void k_gcn_gemm(const float* __restrict__ W) {
    __shared__ float sx[8][DIM];
    int w = threadIdx.x >> 5, lane = threadIdx.x & 31;
    int r0 = blockIdx.x * 8 + w * 2;
    reinterpret_cast<float4*>(sx[w * 2])[lane]     = reinterpret_cast<const float4*>(d_h + (size_t)r0 * DIM)[lane];
    reinterpret_cast<float4*>(sx[w * 2 + 1])[lane] = reinterpret_cast<const float4*>(d_h + (size_t)(r0 + 1) * DIM)[lane];
    __syncwarp();
    const float4* W4 = reinterpret_cast<const float4*>(W);
    float4 aA = make_float4(0.f, 0.f, 0.f, 0.f);
    float4 aB = make_float4(0.f, 0.f, 0.f, 0.f);
#pragma unroll 4
    for (int k = 0; k < DIM; k++) {
        float4 wv = W4[k * 32 + lane];
        float xa = sx[w * 2][k], xb = sx[w * 2 + 1][k];
        aA.x += xa * wv.x; aA.y += xa * wv.y; aA.z += xa * wv.z; aA.w += xa * wv.w;
        aB.x += xb * wv.x; aB.y += xb * wv.y; aB.z += xb * wv.z; aB.w += xb * wv.w;
    }
    reinterpret_cast<float4*>(d_hw + (size_t)r0 * DIM)[lane]       = aA;
    reinterpret_cast<float4*>(d_hw + (size_t)(r0 + 1) * DIM)[lane] = aB;
}

// ---------------- gather4: GCN aggregate + bias/elu/bn2 + gate ----------------
__global__ __launch_bounds__(256) void k_gather4(const float* __restrict__ gcn_b,
                                                 const float* __restrict__ g2, const float* __restrict__ b2,
                                                 const float* __restrict__ m2, const float* __restrict__ v2,
                                                 const float* __restrict__ gateW, const float* __restrict__ gate_b) {
    int w = threadIdx.x >> 5, lane = threadIdx.x & 31;
    (void)w;
    int n = blockIdx.x * 8 + (threadIdx.x >> 5);
    if (n >= Nn) return;
    int row = d_off[n], end = d_off[n + 1], len = end - row;
    float dn = d_dinv[n];
    float a0 = 0.f, a1 = 0.f, a2 = 0.f, a3 = 0.f;
    for (int j = 0; j < len; j++) {
        int sI = d_srcs[row + j];
        float wgt = d_dinv[sI] * dn;
        const float* xs = d_hw + (size_t)sI * DIM;
        a0 += xs[lane]      * wgt;
        a1 += xs[lane + 32] * wgt;
        a2 += xs[lane + 64] * wgt;
        a3 += xs[lane + 96] * wgt;
    }
    float acc[4] = {a0, a1, a2, a3};
    float p = 0.f;
#pragma unroll
    for (int hd = 0; hd < 4; hd++) {
        int c = lane + 32 * hd;
        float v = acc[hd] + gcn_b[c];
        v = v > 0.f ? v : (__expf(v) - 1.0f);
        v = g2[c] * (v - m2[c]) * rsqrtf(v2[c] + 1e-5f) + b2[c];
        d_h2[(size_t)n * DIM + c] = v;
        p += v * gateW[c];
    }
#pragma unroll
    for (int o = 16; o; o >>= 1) p += __shfl_xor_sync(0xffffffffu, p, o);
    if (lane == 0) d_gate[n] = p + gate_b[0];
}

// ---------------- pooling: per-graph softmax + weighted sum (batch sorted) ----------------
__global__ __launch_bounds__(128) void k_pool(const int* __restrict__ batch) {
    __shared__ int sr[2];
    __shared__ float smax[4], ssum[4];
    int b = blockIdx.x;
    int tid = threadIdx.x, lane = tid & 31, wid = tid >> 5;
    if (tid == 0) {
        // lower_bound(b), lower_bound(b+1)
        int lo = 0, hi = Nn;
        while (lo < hi) { int m = (lo + hi) >> 1; if (batch[m] < b) lo = m + 1; else hi = m; }
        sr[0] = lo;
        int lo2 = lo, hi2 = Nn;
        while (lo2 < hi2) { int m = (lo2 + hi2) >> 1; if (batch[m] < b + 1) lo2 = m + 1; else hi2 = m; }
        sr[1] = lo2;
    }
    __syncthreads();
    int lo = sr[0], hi = sr[1];
    if (lo >= hi) { d_grep[(size_t)b * DIM + tid] = 0.f; return; }
    // max
    float mv = -1e30f;
    for (int n = lo + tid; n < hi; n += 128) mv = fmaxf(mv, d_gate[n]);
#pragma unroll
    for (int o = 16; o; o >>= 1) mv = fmaxf(mv, __shfl_xor_sync(0xffffffffu, mv, o));
    if (lane == 0) smax[wid] = mv;
    __syncthreads();
    mv = fmaxf(fmaxf(smax[0], smax[1]), fmaxf(smax[2], smax[3]));
    // sum
    float sv = 0.f;
    for (int n = lo + tid; n < hi; n += 128) sv += __expf(d_gate[n] - mv);
#pragma unroll
    for (int o = 16; o; o >>= 1) sv += __shfl_xor_sync(0xffffffffu, sv, o);
    if (lane == 0) ssum[wid] = sv;
    __syncthreads();
    sv = ssum[0] + ssum[1] + ssum[2] + ssum[3];
    float rcp = 1.0f / (sv + 1e-16f);
    // weighted feature sum: thread tid owns column tid
    float acc = 0.f;
    for (int n = lo; n < hi; n++) {
        float wn = __expf(d_gate[n] - mv) * rcp;
        acc += wn * d_h2[(size_t)n * DIM + tid];
    }
    d_grep[(size_t)b * DIM + tid] = acc;
}

// ---------------- LSTM input projection ----------------
__global__ void k_xpre(const float* __restrict__ quant, const float* __restrict__ Wih,
                       const float* __restrict__ bih, const float* __restrict__ bhh) {
    __shared__ float4 sq[32][8];
    int t = blockIdx.x;
    int bbase = blockIdx.y * 32;
    int tid = threadIdx.x;  // 512
    for (int i = tid; i < 32 * 8; i += 512) {
        int b = i >> 3, k = i & 7;
        sq[b][k] = reinterpret_cast<const float4*>(quant + ((size_t)(bbase + b) * Tt + t) * QD)[k];
    }
    __syncthreads();
    int j = tid;
    float wr[QD];
#pragma unroll
    for (int k = 0; k < QD; k++) wr[k] = Wih[j * QD + k];
    float bs = bih[j] + bhh[j];
    float* outp = d_xpre + ((size_t)t * 512 + j) * Bb + bbase;
    for (int b = 0; b < 32; b++) {
        float acc = bs;
#pragma unroll
        for (int k8 = 0; k8 < 8; k8++) {
            float4 q = sq[b][k8];
            acc += q.x * wr[k8 * 4] + q.y * wr[k8 * 4 + 1] + q.z * wr[k8 * 4 + 2] + q.w * wr[k8 * 4 + 3];
        }
        outp[b] = acc;
    }
}

// ---------------- LSTM step ----------------
__global__ __launch_bounds__(256) void k_lstm_step(const float* __restrict__ Whh, int t) {
    __shared__ float sh[LH][33];
    __shared__ float sW[4][8][LH];
    const float* hprev = (t & 1) ? d_hl1 : d_hl0;
    float* hnew = (t & 1) ? d_hl0 : d_hl1;
    int ugrp = blockIdx.x & 15, bgrp = blockIdx.x >> 4;
    int ubase = ugrp * 8, bbase = bgrp * 32;
    int tid = threadIdx.x;  // 256
    for (int i = tid; i < LH * 32; i += 256) {
        int k = i >> 5, bl = i & 31;
        sh[k][bl] = hprev[k * Bb + bbase + bl];
    }
    for (int i = tid; i < 32 * LH; i += 256) {
        int rl = i >> 7, k = i & 127;
        int g = rl >> 3, uu = rl & 7;
        sW[g][uu][k] = Whh[(g * LH + ubase + uu) * LH + k];
    }
    __syncthreads();
    int uu = tid >> 5, bl = tid & 31;
    int u = ubase + uu, b = bbase + bl;
    const float* xp = d_xpre + (size_t)t * 512 * Bb;
    float a0 = xp[(0 * LH + u) * Bb + b];
    float a1 = xp[(1 * LH + u) * Bb + b];
    float a2 = xp[(2 * LH + u) * Bb + b];
    float a3 = xp[(3 * LH + u) * Bb + b];
#pragma unroll 4
    for (int k = 0; k < LH; k++) {
        float hv = sh[k][bl];
        a0 += hv * sW[0][uu][k];
        a1 += hv * sW[1][uu][k];
        a2 += hv * sW[2][uu][k];
        a3 += hv * sW[3][uu][k];
    }
    float iv = sigf(a0);
    float fv = sigf(a1);
    float gv = tanhf(a2);
    float ov = sigf(a3);
    int ci = u * Bb + b;
    float cc = fv * d_cl[ci] + iv * gv;
    d_cl[ci] = cc;
    hnew[ci] = ov * tanhf(cc);
}

// ---------------- final linear ----------------
__global__ void k_final(const float* __restrict__ fcW, const float* __restrict__ fcb,
                        float* __restrict__ out) {
    int b = threadIdx.x;  // 256
    const float* hT = d_hl0;  // t=49 (odd) writes into d_hl0
    float acc = fcb[0];
#pragma unroll 4
    for (int c = 0; c < DIM; c++) acc += d_grep[b * DIM + c] * fcW[c];
#pragma unroll 4
    for (int u = 0; u < LH; u++) acc += hT[u * Bb + b] * fcW[DIM + u];
    out[b] = acc;
}

// ---------------- launch ----------------
extern "C" void kernel_launch(void* const* d_in, const int* in_sizes, int n_in,
                              void* d_out, int out_size) {
    (void)in_sizes; (void)n_in; (void)out_size;
    const float* x       = (const float*)d_in[0];
    const int*   ei      = (const int*)d_in[1];
    const int*   batch   = (const int*)d_in[2];
    const float* quant   = (const float*)d_in[3];
    const float* gat_W   = (const float*)d_in[4];
    const float* att_src = (const float*)d_in[5];
    const float* att_dst = (const float*)d_in[6];
    const float* gat_b   = (const float*)d_in[7];
    const float* bn1_g   = (const float*)d_in[8];
    const float* bn1_b   = (const float*)d_in[9];
    const float* bn1_m   = (const float*)d_in[10];
    const float* bn1_v   = (const float*)d_in[11];
    const float* gcn_W   = (const float*)d_in[12];
    const float* gcn_b   = (const float*)d_in[13];
    const float* bn2_g   = (const float*)d_in[14];
    const float* bn2_b   = (const float*)d_in[15];
    const float* bn2_m   = (const float*)d_in[16];
    const float* bn2_v   = (const float*)d_in[17];
    const float* gate_W  = (const float*)d_in[18];
    const float* gate_b  = (const float*)d_in[19];
    const float* Wih     = (const float*)d_in[20];
    const float* Whh     = (const float*)d_in[21];
    const float* bih     = (const float*)d_in[22];
    const float* bhh     = (const float*)d_in[23];
    const float* fcW     = (const float*)d_in[24];
    const float* fcb     = (const float*)d_in[25];
    float* out = (float*)d_out;

    static cudaStream_t s_lstm = nullptr;
    static cudaEvent_t evA = nullptr, evB = nullptr;
    if (s_lstm == nullptr) {
        cudaStreamCreateWithFlags(&s_lstm, cudaStreamNonBlocking);
        cudaEventCreateWithFlags(&evA, cudaEventDisableTiming);
        cudaEventCreateWithFlags(&evB, cudaEventDisableTiming);
    }

    k_init<<<128, 512>>>();

    // fork: LSTM branch on side stream (depends only on quant + zeroed state)
    cudaEventRecord(evA, 0);
    cudaStreamWaitEvent(s_lstm, evA, 0);
    k_xpre<<<dim3(Tt, Bb / 32), 512, 0, s_lstm>>>(quant, Wih, bih, bhh);
    for (int t = 0; t < Tt; t++) {
        k_lstm_step<<<128, 256, 0, s_lstm>>>(Whh, t);
    }
    cudaEventRecord(evB, s_lstm);

    // graph branch on main stream
    k_gat_gemm<<<Nn / 8, 128>>>(x, gat_W, att_src, att_dst);
    k_count<<<(NeT + 255) / 256, 256>>>(ei);
    k_scan1<<<SCAN_B, 512>>>();
    k_scan2<<<1, 32>>>();
    k_scan3<<<SCAN_B, 512>>>();
    k_scatter<<<(NeT + 255) / 256, 256>>>(ei);
    k_gather3<<<(Nn + 7) / 8, 256>>>(gat_b, bn1_g, bn1_b, bn1_m, bn1_v);
    k_gcn_gemm<<<Nn / 8, 128>>>(gcn_W);
    k_gather4<<<(Nn + 7) / 8, 256>>>(gcn_b, bn2_g, bn2_b, bn2_m, bn2_v, gate_W, gate_b);
    k_pool<<<Bb, 128>>>(batch);

    // join
    cudaStreamWaitEvent(0, evB, 0);
    k_final<<<1, 256>>>(fcW, fcb, out);
}

// round 4
// speedup vs baseline: 2.3781x; 1.7140x over previous
#include <cuda_runtime.h>
#include <math.h>

// ---------------- problem constants ----------------
constexpr int Nn  = 50000;     // nodes
constexpr int Ne  = 800000;    // edges (without self loops)
constexpr int NeT = 850000;    // edges + self loops
constexpr int Bb  = 256;       // graphs / batch
constexpr int Tt  = 50;        // timesteps
constexpr int DIM = 128;       // feature dim (H*C1 == C2 == 128)
constexpr int LH  = 128;       // lstm hidden
constexpr int QD  = 32;        // lstm input dim
constexpr int CAP = 64;        // per-row smem edge cache
constexpr int SCAN_B = (Nn + 511) / 512;   // 98
constexpr int LCTAS = 128;     // persistent LSTM CTAs
constexpr int BPC = Bb / LCTAS; // 2 batches per CTA

// dynamic smem layout for k_lstm_persist (floats):
//   s_w    : 512 * 68   (Whh k=64..127 half, padded row)
//   s_h    : BPC * 128
//   s_gate : BPC * 512
constexpr int SW_FLOATS = 512 * 68;
constexpr int SH_FLOATS = BPC * 128;
constexpr int SG_FLOATS = BPC * 512;
constexpr int LSTM_SMEM_BYTES = (SW_FLOATS + SH_FLOATS + SG_FLOATS) * 4;  // ~144.4 KB

// ---------------- device scratch ----------------
__device__ float    d_xw[Nn * DIM];
__device__ float    d_asrc[Nn * 4];
__device__ float    d_adst[Nn * 4];
__device__ int      d_degi[Nn];
__device__ int      d_cnt[Nn];
__device__ int      d_off[Nn + 1];
__device__ int      d_bsum[SCAN_B];
__device__ int      d_bsx[SCAN_B];
__device__ int      d_srcs[NeT];
__device__ float    d_escr[NeT * 4];
__device__ float    d_h[Nn * DIM];
__device__ float    d_dinv[Nn];
__device__ float    d_hw[Nn * DIM];
__device__ float    d_h2[Nn * DIM];
__device__ float    d_gate[Nn];
__device__ float    d_grep[Bb * DIM];
__device__ float    d_xpre[Bb * Tt * 4 * LH];  // [b][t][gate*128+u]
__device__ float    d_hT[LH * Bb];             // final h, [u][b]

__device__ __forceinline__ float sigf(float x) { return 1.0f / (1.0f + __expf(-x)); }

// ---------------- init ----------------
__global__ void k_init() {
    int i = blockIdx.x * blockDim.x + threadIdx.x;
    if (i < Nn) { d_degi[i] = 0; d_cnt[i] = 0; }
}

// ---------------- GAT gemm ----------------
__global__ void k_gat_gemm(const float* __restrict__ x, const float* __restrict__ W,
                           const float* __restrict__ att_s, const float* __restrict__ att_d) {
    __shared__ float sx[8][DIM];
    int w = threadIdx.x >> 5, lane = threadIdx.x & 31;
    int r0 = blockIdx.x * 8 + w * 2;
    reinterpret_cast<float4*>(sx[w * 2])[lane]     = reinterpret_cast<const float4*>(x + (size_t)r0 * DIM)[lane];
    reinterpret_cast<float4*>(sx[w * 2 + 1])[lane] = reinterpret_cast<const float4*>(x + (size_t)(r0 + 1) * DIM)[lane];
    __syncwarp();
    const float4* W4 = reinterpret_cast<const float4*>(W);
    float4 aA = make_float4(0.f, 0.f, 0.f, 0.f);
    float4 aB = make_float4(0.f, 0.f, 0.f, 0.f);
#pragma unroll 4
    for (int k = 0; k < DIM; k++) {
        float4 wv = W4[k * 32 + lane];
        float xa = sx[w * 2][k], xb = sx[w * 2 + 1][k];
        aA.x += xa * wv.x; aA.y += xa * wv.y; aA.z += xa * wv.z; aA.w += xa * wv.w;
        aB.x += xb * wv.x; aB.y += xb * wv.y; aB.z += xb * wv.z; aB.w += xb * wv.w;
    }
    reinterpret_cast<float4*>(d_xw + (size_t)r0 * DIM)[lane]       = aA;
    reinterpret_cast<float4*>(d_xw + (size_t)(r0 + 1) * DIM)[lane] = aB;
    int c0 = lane * 4;
    float s0 = att_s[c0], s1 = att_s[c0 + 1], s2 = att_s[c0 + 2], s3 = att_s[c0 + 3];
    float d0 = att_d[c0], d1 = att_d[c0 + 1], d2 = att_d[c0 + 2], d3 = att_d[c0 + 3];
#pragma unroll
    for (int r = 0; r < 2; r++) {
        float4 a = r ? aB : aA;
        float ps = a.x * s0 + a.y * s1 + a.z * s2 + a.w * s3;
        float pd = a.x * d0 + a.y * d1 + a.z * d2 + a.w * d3;
#pragma unroll
        for (int off = 4; off; off >>= 1) {
            ps += __shfl_xor_sync(0xffffffffu, ps, off);
            pd += __shfl_xor_sync(0xffffffffu, pd, off);
        }
        if ((lane & 7) == 0) {
            int h = lane >> 3;
            d_asrc[(r0 + r) * 4 + h] = ps;
            d_adst[(r0 + r) * 4 + h] = pd;
        }
    }
}

// ---------------- CSR build ----------------
__global__ void k_count(const int* __restrict__ ei) {
    int e = blockIdx.x * blockDim.x + threadIdx.x;
    if (e >= NeT) return;
    int d = (e < Ne) ? ei[Ne + e] : e - Ne;
    atomicAdd(&d_degi[d], 1);
}

__global__ void k_scan1() {
    __shared__ int wsum[16];
    int i = blockIdx.x * 512 + threadIdx.x;
    int v = (i < Nn) ? d_degi[i] : 0;
    int lane = threadIdx.x & 31, wid = threadIdx.x >> 5;
    int inc = v;
#pragma unroll
    for (int o = 1; o < 32; o <<= 1) {
        int t = __shfl_up_sync(0xffffffffu, inc, o);
        if (lane >= o) inc += t;
    }
    if (lane == 31) wsum[wid] = inc;
    __syncthreads();
    if (wid == 0) {
        int wv = (lane < 16) ? wsum[lane] : 0;
#pragma unroll
        for (int o = 1; o < 16; o <<= 1) {
            int t = __shfl_up_sync(0xffffffffu, wv, o);
            if (lane >= o) wv += t;
        }
        if (lane < 16) wsum[lane] = wv;
    }
    __syncthreads();
    int woff = (wid > 0) ? wsum[wid - 1] : 0;
    if (i < Nn) d_off[i] = woff + inc - v;
    if (threadIdx.x == 0) d_bsum[blockIdx.x] = wsum[15];
}

__global__ void k_scan2() {
    if (threadIdx.x != 0 || blockIdx.x != 0) return;
    int run = 0;
    for (int i = 0; i < SCAN_B; i++) { int t = d_bsum[i]; d_bsx[i] = run; run += t; }
}

__global__ void k_scan3() {
    int i = blockIdx.x * 512 + threadIdx.x;
    if (i < Nn) d_off[i] += d_bsx[blockIdx.x];
    if (i == 0) d_off[Nn] = NeT;
}

__global__ void k_scatter(const int* __restrict__ ei) {
    int e = blockIdx.x * blockDim.x + threadIdx.x;
    if (e >= NeT) return;
    int s, d;
    if (e < Ne) { s = ei[e]; d = ei[Ne + e]; } else { s = d = e - Ne; }
    float4 as = *reinterpret_cast<const float4*>(d_asrc + s * 4);
    float4 ad = *reinterpret_cast<const float4*>(d_adst + d * 4);
    float4 v;
    v.x = as.x + ad.x; v.y = as.y + ad.y; v.z = as.z + ad.z; v.w = as.w + ad.w;
    v.x = v.x > 0.f ? v.x : 0.2f * v.x;
    v.y = v.y > 0.f ? v.y : 0.2f * v.y;
    v.z = v.z > 0.f ? v.z : 0.2f * v.z;
    v.w = v.w > 0.f ? v.w : 0.2f * v.w;
    int pos = d_off[d] + atomicAdd(&d_cnt[d], 1);
    d_srcs[pos] = s;
    *reinterpret_cast<float4*>(d_escr + (size_t)pos * 4) = v;
}

// ---------------- gather3: softmax + aggregate + bias/elu/bn1 + dinv ----------------
__global__ __launch_bounds__(256) void k_gather3(const float* __restrict__ gat_b,
                                                 const float* __restrict__ g1, const float* __restrict__ b1,
                                                 const float* __restrict__ m1, const float* __restrict__ v1) {
    __shared__ float sex[8][CAP * 4];
    int w = threadIdx.x >> 5, lane = threadIdx.x & 31;
    int n = blockIdx.x * 8 + w;
    if (n >= Nn) return;
    int row = d_off[n], end = d_off[n + 1], len = end - row;

    float m0 = -1e30f, m1v = -1e30f, m2v = -1e30f, m3v = -1e30f;
    for (int base = 0; base < len; base += 32) {
        int j = base + lane;
        if (j < len) {
            float4 v = *reinterpret_cast<const float4*>(d_escr + (size_t)(row + j) * 4);
            if (j < CAP) *reinterpret_cast<float4*>(&sex[w][j * 4]) = v;
            m0 = fmaxf(m0, v.x); m1v = fmaxf(m1v, v.y); m2v = fmaxf(m2v, v.z); m3v = fmaxf(m3v, v.w);
        }
    }
#pragma unroll
    for (int o = 16; o; o >>= 1) {
        m0  = fmaxf(m0,  __shfl_xor_sync(0xffffffffu, m0,  o));
        m1v = fmaxf(m1v, __shfl_xor_sync(0xffffffffu, m1v, o));
        m2v = fmaxf(m2v, __shfl_xor_sync(0xffffffffu, m2v, o));
        m3v = fmaxf(m3v, __shfl_xor_sync(0xffffffffu, m3v, o));
    }
    float s0 = 0.f, s1 = 0.f, s2 = 0.f, s3 = 0.f;
    for (int base = 0; base < len; base += 32) {
        int j = base + lane;
        if (j < len) {
            float4 v;
            if (j < CAP) v = *reinterpret_cast<float4*>(&sex[w][j * 4]);
            else         v = *reinterpret_cast<const float4*>(d_escr + (size_t)(row + j) * 4);
            v.x = __expf(v.x - m0);  v.y = __expf(v.y - m1v);
            v.z = __expf(v.z - m2v); v.w = __expf(v.w - m3v);
            if (j < CAP) *reinterpret_cast<float4*>(&sex[w][j * 4]) = v;
            s0 += v.x; s1 += v.y; s2 += v.z; s3 += v.w;
        }
    }
#pragma unroll
    for (int o = 16; o; o >>= 1) {
        s0 += __shfl_xor_sync(0xffffffffu, s0, o);
        s1 += __shfl_xor_sync(0xffffffffu, s1, o);
        s2 += __shfl_xor_sync(0xffffffffu, s2, o);
        s3 += __shfl_xor_sync(0xffffffffu, s3, o);
    }
    float r0 = 1.0f / (s0 + 1e-16f), r1 = 1.0f / (s1 + 1e-16f);
    float r2 = 1.0f / (s2 + 1e-16f), r3 = 1.0f / (s3 + 1e-16f);

    __syncwarp();
    float a0 = 0.f, a1 = 0.f, a2 = 0.f, a3 = 0.f;
    for (int j = 0; j < len; j++) {
        int sI = d_srcs[row + j];
        float w0, w1, w2, w3;
        if (j < CAP) {
            w0 = sex[w][j * 4 + 0] * r0; w1 = sex[w][j * 4 + 1] * r1;
            w2 = sex[w][j * 4 + 2] * r2; w3 = sex[w][j * 4 + 3] * r3;
        } else {
            float4 v = *reinterpret_cast<const float4*>(d_escr + (size_t)(row + j) * 4);
            w0 = __expf(v.x - m0)  * r0; w1 = __expf(v.y - m1v) * r1;
            w2 = __expf(v.z - m2v) * r2; w3 = __expf(v.w - m3v) * r3;
        }
        const float* xs = d_xw + (size_t)sI * DIM;
        a0 += xs[lane]      * w0;
        a1 += xs[lane + 32] * w1;
        a2 += xs[lane + 64] * w2;
        a3 += xs[lane + 96] * w3;
    }
    float acc[4] = {a0, a1, a2, a3};
#pragma unroll
    for (int hd = 0; hd < 4; hd++) {
        int c = lane + 32 * hd;
        float v = acc[hd] + gat_b[c];
        v = v > 0.f ? v : (__expf(v) - 1.0f);
        v = g1[c] * (v - m1[c]) * rsqrtf(v1[c] + 1e-5f) + b1[c];
        d_h[(size_t)n * DIM + c] = v;
    }
    if (lane == 0) d_dinv[n] = rsqrtf((float)len);
}

// ---------------- GCN gemm ----------------
__global__ void k_gcn_gemm(const float* __restrict__ W) {
    __shared__ float sx[8][DIM];
    int w = threadIdx.x >> 5, lane = threadIdx.x & 31;
    int r0 = blockIdx.x * 8 + w * 2;
    reinterpret_cast<float4*>(sx[w * 2])[lane]     = reinterpret_cast<const float4*>(d_h + (size_t)r0 * DIM)[lane];
    reinterpret_cast<float4*>(sx[w * 2 + 1])[lane] = reinterpret_cast<const float4*>(d_h + (size_t)(r0 + 1) * DIM)[lane];
    __syncwarp();
    const float4* W4 = reinterpret_cast<const float4*>(W);
    float4 aA = make_float4(0.f, 0.f, 0.f, 0.f);
    float4 aB = make_float4(0.f, 0.f, 0.f, 0.f);
#pragma unroll 4
    for (int k = 0; k < DIM; k++) {
        float4 wv = W4[k * 32 + lane];
        float xa = sx[w * 2][k], xb = sx[w * 2 + 1][k];
        aA.x += xa * wv.x; aA.y += xa * wv.y; aA.z += xa * wv.z; aA.w += xa * wv.w;
        aB.x += xb * wv.x; aB.y += xb * wv.y; aB.z += xb * wv.z; aB.w += xb * wv.w;
    }
    reinterpret_cast<float4*>(d_hw + (size_t)r0 * DIM)[lane]       = aA;
    reinterpret_cast<float4*>(d_hw + (size_t)(r0 + 1) * DIM)[lane] = aB;
}

// ---------------- gather4: GCN aggregate + bias/elu/bn2 + gate ----------------
__global__ __launch_bounds__(256) void k_gather4(const float* __restrict__ gcn_b,
                                                 const float* __restrict__ g2, const float* __restrict__ b2,
                                                 const float* __restrict__ m2, const float* __restrict__ v2,
                                                 const float* __restrict__ gateW, const float* __restrict__ gate_b) {
    int lane = threadIdx.x & 31;
    int n = blockIdx.x * 8 + (threadIdx.x >> 5);
    if (n >= Nn) return;
    int row = d_off[n], end = d_off[n + 1], len = end - row;
    float dn = d_dinv[n];
    float a0 = 0.f, a1 = 0.f, a2 = 0.f, a3 = 0.f;
    for (int j = 0; j < len; j++) {
        int sI = d_srcs[row + j];
        float wgt = d_dinv[sI] * dn;
        const float* xs = d_hw + (size_t)sI * DIM;
        a0 += xs[lane]      * wgt;
        a1 += xs[lane + 32] * wgt;
        a2 += xs[lane + 64] * wgt;
        a3 += xs[lane + 96] * wgt;
    }
    float acc[4] = {a0, a1, a2, a3};
    float p = 0.f;
#pragma unroll
    for (int hd = 0; hd < 4; hd++) {
        int c = lane + 32 * hd;
        float v = acc[hd] + gcn_b[c];
        v = v > 0.f ? v : (__expf(v) - 1.0f);
        v = g2[c] * (v - m2[c]) * rsqrtf(v2[c] + 1e-5f) + b2[c];
        d_h2[(size_t)n * DIM + c] = v;
        p += v * gateW[c];
    }
#pragma unroll
    for (int o = 16; o; o >>= 1) p += __shfl_xor_sync(0xffffffffu, p, o);
    if (lane == 0) d_gate[n] = p + gate_b[0];
}

// ---------------- pooling ----------------
__global__ __launch_bounds__(128) void k_pool(const int* __restrict__ batch) {
    __shared__ int sr[2];
    __shared__ float smax[4], ssum[4];
    int b = blockIdx.x;
    int tid = threadIdx.x, lane = tid & 31, wid = tid >> 5;
    if (tid == 0) {
        int lo = 0, hi = Nn;
        while (lo < hi) { int m = (lo + hi) >> 1; if (batch[m] < b) lo = m + 1; else hi = m; }
        sr[0] = lo;
        int lo2 = lo, hi2 = Nn;
        while (lo2 < hi2) { int m = (lo2 + hi2) >> 1; if (batch[m] < b + 1) lo2 = m + 1; else hi2 = m; }
        sr[1] = lo2;
    }
    __syncthreads();
    int lo = sr[0], hi = sr[1];
    if (lo >= hi) { d_grep[(size_t)b * DIM + tid] = 0.f; return; }
    float mv = -1e30f;
    for (int n = lo + tid; n < hi; n += 128) mv = fmaxf(mv, d_gate[n]);
#pragma unroll
    for (int o = 16; o; o >>= 1) mv = fmaxf(mv, __shfl_xor_sync(0xffffffffu, mv, o));
    if (lane == 0) smax[wid] = mv;
    __syncthreads();
    mv = fmaxf(fmaxf(smax[0], smax[1]), fmaxf(smax[2], smax[3]));
    float sv = 0.f;
    for (int n = lo + tid; n < hi; n += 128) sv += __expf(d_gate[n] - mv);
#pragma unroll
    for (int o = 16; o; o >>= 1) sv += __shfl_xor_sync(0xffffffffu, sv, o);
    if (lane == 0) ssum[wid] = sv;
    __syncthreads();
    sv = ssum[0] + ssum[1] + ssum[2] + ssum[3];
    float rcp = 1.0f / (sv + 1e-16f);
    float acc = 0.f;
    for (int n = lo; n < hi; n++) {
        float wn = __expf(d_gate[n] - mv) * rcp;
        acc += wn * d_h2[(size_t)n * DIM + tid];
    }
    d_grep[(size_t)b * DIM + tid] = acc;
}

// ---------------- LSTM input projection: xpre[b][t][j] ----------------
__global__ void k_xpre(const float* __restrict__ quant, const float* __restrict__ Wih,
                       const float* __restrict__ bih, const float* __restrict__ bhh) {
    __shared__ float4 sq[32][8];
    int t = blockIdx.x;
    int bbase = blockIdx.y * 32;
    int tid = threadIdx.x;  // 512
    for (int i = tid; i < 32 * 8; i += 512) {
        int b = i >> 3, k = i & 7;
        sq[b][k] = reinterpret_cast<const float4*>(quant + ((size_t)(bbase + b) * Tt + t) * QD)[k];
    }
    __syncthreads();
    int j = tid;
    float wr[QD];
#pragma unroll
    for (int k = 0; k < QD; k++) wr[k] = Wih[j * QD + k];
    float bs = bih[j] + bhh[j];
    for (int b = 0; b < 32; b++) {
        float acc = bs;
#pragma unroll
        for (int k8 = 0; k8 < 8; k8++) {
            float4 q = sq[b][k8];
            acc += q.x * wr[k8 * 4] + q.y * wr[k8 * 4 + 1] + q.z * wr[k8 * 4 + 2] + q.w * wr[k8 * 4 + 3];
        }
        d_xpre[((size_t)(bbase + b) * Tt + t) * 512 + j] = acc;
    }
}

// ---------------- persistent LSTM: one CTA per 2 batches, all 50 steps ----------------
// dynamic smem: s_w[512][68] | s_h[BPC][128] | s_gate[BPC][512]
__global__ __launch_bounds__(512) void k_lstm_persist(const float* __restrict__ Whh) {
    extern __shared__ float dyn[];
    float* s_w    = dyn;                         // [512][68]
    float* s_h    = dyn + SW_FLOATS;             // [BPC][128]
    float* s_gate = dyn + SW_FLOATS + SH_FLOATS; // [BPC][512]
    int j = threadIdx.x;                         // gate-row 0..511

    // register half: k = 0..63
    float4 w4[16];
    const float4* Wr = reinterpret_cast<const float4*>(Whh + (size_t)j * 128);
#pragma unroll
    for (int q = 0; q < 16; q++) w4[q] = Wr[q];
    // smem half: k = 64..127
#pragma unroll
    for (int q = 0; q < 16; q++) {
        float4 v = Wr[16 + q];
        *reinterpret_cast<float4*>(&s_w[j * 68 + q * 4]) = v;
    }
    if (j < BPC * 128) s_h[j] = 0.f;
    float c0 = 0.f, c1 = 0.f;                    // cell state (threads < 256)
    __syncthreads();

    int bglob = blockIdx.x * BPC;
    const float* xp0 = d_xpre + (size_t)(bglob + 0) * Tt * 512;
    const float* xp1 = d_xpre + (size_t)(bglob + 1) * Tt * 512;

    for (int t = 0; t < Tt; t++) {
        float x0 = xp0[t * 512 + j];
        float x1 = xp1[t * 512 + j];
        float a0 = 0.f, a1 = 0.f;
#pragma unroll
        for (int q = 0; q < 16; q++) {
            float4 h0 = *reinterpret_cast<const float4*>(&s_h[0 * 128 + q * 4]);
            float4 h1 = *reinterpret_cast<const float4*>(&s_h[1 * 128 + q * 4]);
            float4 wv = w4[q];
            a0 += wv.x * h0.x + wv.y * h0.y + wv.z * h0.z + wv.w * h0.w;
            a1 += wv.x * h1.x + wv.y * h1.y + wv.z * h1.z + wv.w * h1.w;
        }
#pragma unroll
        for (int q = 0; q < 16; q++) {
            float4 wv = *reinterpret_cast<const float4*>(&s_w[j * 68 + q * 4]);
            float4 h0 = *reinterpret_cast<const float4*>(&s_h[0 * 128 + 64 + q * 4]);
            float4 h1 = *reinterpret_cast<const float4*>(&s_h[1 * 128 + 64 + q * 4]);
            a0 += wv.x * h0.x + wv.y * h0.y + wv.z * h0.z + wv.w * h0.w;
            a1 += wv.x * h1.x + wv.y * h1.y + wv.z * h1.z + wv.w * h1.w;
        }
        s_gate[0 * 512 + j] = a0 + x0;
        s_gate[1 * 512 + j] = a1 + x1;
        __syncthreads();
        if (j < 256) {
            int b = j >> 7, u = j & 127;
            float gi = s_gate[b * 512 + u];
            float gf = s_gate[b * 512 + 128 + u];
            float gg = s_gate[b * 512 + 256 + u];
            float go = s_gate[b * 512 + 384 + u];
            float cv = (j < 128) ? c0 : c1;
            cv = sigf(gf) * cv + sigf(gi) * tanhf(gg);
            if (j < 128) c0 = cv; else c1 = cv;
            s_h[b * 128 + u] = sigf(go) * tanhf(cv);
        }
        __syncthreads();
    }
    if (j < BPC * 128) {
        int b = j >> 7, u = j & 127;
        d_hT[u * Bb + (bglob + b)] = s_h[b * 128 + u];
    }
}

// ---------------- final linear ----------------
__global__ void k_final(const float* __restrict__ fcW, const float* __restrict__ fcb,
                        float* __restrict__ out) {
    int b = threadIdx.x;  // 256
    float acc = fcb[0];
#pragma unroll 4
    for (int c = 0; c < DIM; c++) acc += d_grep[b * DIM + c] * fcW[c];
#pragma unroll 4
    for (int u = 0; u < LH; u++) acc += d_hT[u * Bb + b] * fcW[DIM + u];
    out[b] = acc;
}

// ---------------- launch ----------------
extern "C" void kernel_launch(void* const* d_in, const int* in_sizes, int n_in,
                              void* d_out, int out_size) {
    (void)in_sizes; (void)n_in; (void)out_size;
    const float* x       = (const float*)d_in[0];
    const int*   ei      = (const int*)d_in[1];
    const int*   batch   = (const int*)d_in[2];
    const float* quant   = (const float*)d_in[3];
    const float* gat_W   = (const float*)d_in[4];
    const float* att_src = (const float*)d_in[5];
    const float* att_dst = (const float*)d_in[6];
    const float* gat_b   = (const float*)d_in[7];
    const float* bn1_g   = (const float*)d_in[8];
    const float* bn1_b   = (const float*)d_in[9];
    const float* bn1_m   = (const float*)d_in[10];
    const float* bn1_v   = (const float*)d_in[11];
    const float* gcn_W   = (const float*)d_in[12];
    const float* gcn_b   = (const float*)d_in[13];
    const float* bn2_g   = (const float*)d_in[14];
    const float* bn2_b   = (const float*)d_in[15];
    const float* bn2_m   = (const float*)d_in[16];
    const float* bn2_v   = (const float*)d_in[17];
    const float* gate_W  = (const float*)d_in[18];
    const float* gate_b  = (const float*)d_in[19];
    const float* Wih     = (const float*)d_in[20];
    const float* Whh     = (const float*)d_in[21];
    const float* bih     = (const float*)d_in[22];
    const float* bhh     = (const float*)d_in[23];
    const float* fcW     = (const float*)d_in[24];
    const float* fcb     = (const float*)d_in[25];
    float* out = (float*)d_out;

    static cudaStream_t s_lstm = nullptr;
    static cudaEvent_t evA = nullptr, evB = nullptr;
    if (s_lstm == nullptr) {
        cudaStreamCreateWithFlags(&s_lstm, cudaStreamNonBlocking);
        cudaEventCreateWithFlags(&evA, cudaEventDisableTiming);
        cudaEventCreateWithFlags(&evB, cudaEventDisableTiming);
        cudaFuncSetAttribute(k_lstm_persist, cudaFuncAttributeMaxDynamicSharedMemorySize, LSTM_SMEM_BYTES);
        cudaFuncSetAttribute(k_lstm_persist, cudaFuncAttributePreferredSharedMemoryCarveout, 100);
    }

    // fork: LSTM branch on side stream
    cudaEventRecord(evA, 0);
    cudaStreamWaitEvent(s_lstm, evA, 0);
    k_xpre<<<dim3(Tt, Bb / 32), 512, 0, s_lstm>>>(quant, Wih, bih, bhh);
    k_lstm_persist<<<LCTAS, 512, LSTM_SMEM_BYTES, s_lstm>>>(Whh);
    cudaEventRecord(evB, s_lstm);

    // graph branch on main stream
    k_init<<<(Nn + 511) / 512, 512>>>();
    k_gat_gemm<<<Nn / 8, 128>>>(x, gat_W, att_src, att_dst);
    k_count<<<(NeT + 255) / 256, 256>>>(ei);
    k_scan1<<<SCAN_B, 512>>>();
    k_scan2<<<1, 32>>>();
    k_scan3<<<SCAN_B, 512>>>();
    k_scatter<<<(NeT + 255) / 256, 256>>>(ei);
    k_gather3<<<(Nn + 7) / 8, 256>>>(gat_b, bn1_g, bn1_b, bn1_m, bn1_v);
    k_gcn_gemm<<<Nn / 8, 128>>>(gcn_W);
    k_gather4<<<(Nn + 7) / 8, 256>>>(gcn_b, bn2_g, bn2_b, bn2_m, bn2_v, gate_W, gate_b);
    k_pool<<<Bb, 128>>>(batch);

    // join
    cudaStreamWaitEvent(0, evB, 0);
    k_final<<<1, 256>>>(fcW, fcb, out);
}

// round 5
// speedup vs baseline: 2.6343x; 1.1077x over previous
#include <cuda_runtime.h>
#include <math.h>

// ---------------- problem constants ----------------
constexpr int Nn  = 50000;     // nodes
constexpr int Ne  = 800000;    // edges (without self loops)
constexpr int NeT = 850000;    // edges + self loops
constexpr int Bb  = 256;       // graphs / batch
constexpr int Tt  = 50;        // timesteps
constexpr int DIM = 128;       // feature dim (H*C1 == C2 == 128)
constexpr int LH  = 128;       // lstm hidden
constexpr int QD  = 32;        // lstm input dim
constexpr int CAP = 64;        // per-row smem edge cache
constexpr int SCAN_B = (Nn + 511) / 512;   // 98
constexpr int LCTAS = 128;     // persistent LSTM CTAs
constexpr int BPC = Bb / LCTAS; // 2 batches per CTA

// dynamic smem layout for k_lstm_persist (floats)
constexpr int SW_FLOATS = 512 * 68;
constexpr int SH_FLOATS = BPC * 128;
constexpr int SG_FLOATS = BPC * 512;
constexpr int LSTM_SMEM_BYTES = (SW_FLOATS + SH_FLOATS + SG_FLOATS) * 4;  // ~144.4 KB

// ---------------- device scratch ----------------
__device__ float    d_xw[Nn * DIM];
__device__ float    d_asrc[Nn * 4];
__device__ float    d_adst[Nn * 4];
__device__ int      d_degi[Nn];
__device__ int      d_cnt[Nn];
__device__ int      d_off[Nn + 1];
__device__ int      d_bsum[SCAN_B];
__device__ int      d_bsx[SCAN_B];
__device__ int      d_srcs[NeT];
__device__ float    d_escr[NeT * 4];
__device__ float    d_h[Nn * DIM];
__device__ float    d_dinv[Nn];
__device__ float    d_hw[Nn * DIM];
__device__ float    d_h2[Nn * DIM];
__device__ float    d_gate[Nn];
__device__ float    d_grep[Bb * DIM];
__device__ float    d_xpre[Bb * Tt * 4 * LH];  // [b][t][gate*128+u]
__device__ float    d_hT[LH * Bb];             // final h, [u][b]

__device__ __forceinline__ float sigf(float x) { return 1.0f / (1.0f + __expf(-x)); }

// ---------------- init ----------------
__global__ void k_init() {
    int i = blockIdx.x * blockDim.x + threadIdx.x;
    if (i < Nn) { d_degi[i] = 0; d_cnt[i] = 0; }
}

// ---------------- GAT gemm: 8 rows/warp, 64 rows/CTA ----------------
__global__ __launch_bounds__(256) void k_gat_gemm(const float* __restrict__ x, const float* __restrict__ W,
                                                  const float* __restrict__ att_s, const float* __restrict__ att_d) {
    __shared__ float sx[64][DIM];
    int tid = threadIdx.x, w = tid >> 5, lane = tid & 31;
    int base = blockIdx.x * 64;
    for (int idx = tid; idx < 64 * 32; idx += 256) {
        int rl = idx >> 5, c4 = idx & 31;
        int gr = base + rl;
        float4 v = (gr < Nn) ? reinterpret_cast<const float4*>(x + (size_t)gr * DIM)[c4]
                             : make_float4(0.f, 0.f, 0.f, 0.f);
        reinterpret_cast<float4*>(sx[rl])[c4] = v;
    }
    __syncthreads();
    const float4* W4 = reinterpret_cast<const float4*>(W);
    float4 acc[8];
#pragma unroll
    for (int r = 0; r < 8; r++) acc[r] = make_float4(0.f, 0.f, 0.f, 0.f);
    int rb = w * 8;
#pragma unroll 4
    for (int k = 0; k < DIM; k++) {
        float4 wv = W4[k * 32 + lane];
#pragma unroll
        for (int r = 0; r < 8; r++) {
            float xk = sx[rb + r][k];
            acc[r].x += xk * wv.x; acc[r].y += xk * wv.y;
            acc[r].z += xk * wv.z; acc[r].w += xk * wv.w;
        }
    }
    int c0 = lane * 4;
    float s0 = att_s[c0], s1 = att_s[c0 + 1], s2 = att_s[c0 + 2], s3 = att_s[c0 + 3];
    float d0 = att_d[c0], d1 = att_d[c0 + 1], d2 = att_d[c0 + 2], d3 = att_d[c0 + 3];
#pragma unroll
    for (int r = 0; r < 8; r++) {
        int gr = base + rb + r;
        if (gr >= Nn) break;
        reinterpret_cast<float4*>(d_xw + (size_t)gr * DIM)[lane] = acc[r];
        float ps = acc[r].x * s0 + acc[r].y * s1 + acc[r].z * s2 + acc[r].w * s3;
        float pd = acc[r].x * d0 + acc[r].y * d1 + acc[r].z * d2 + acc[r].w * d3;
#pragma unroll
        for (int off = 4; off; off >>= 1) {
            ps += __shfl_xor_sync(0xffffffffu, ps, off);
            pd += __shfl_xor_sync(0xffffffffu, pd, off);
        }
        if ((lane & 7) == 0) {
            int h = lane >> 3;
            d_asrc[gr * 4 + h] = ps;
            d_adst[gr * 4 + h] = pd;
        }
    }
}

// ---------------- CSR build ----------------
__global__ void k_count(const int* __restrict__ ei) {
    int e = blockIdx.x * blockDim.x + threadIdx.x;
    if (e >= NeT) return;
    int d = (e < Ne) ? ei[Ne + e] : e - Ne;
    atomicAdd(&d_degi[d], 1);
}

__global__ void k_scan1() {
    __shared__ int wsum[16];
    int i = blockIdx.x * 512 + threadIdx.x;
    int v = (i < Nn) ? d_degi[i] : 0;
    int lane = threadIdx.x & 31, wid = threadIdx.x >> 5;
    int inc = v;
#pragma unroll
    for (int o = 1; o < 32; o <<= 1) {
        int t = __shfl_up_sync(0xffffffffu, inc, o);
        if (lane >= o) inc += t;
    }
    if (lane == 31) wsum[wid] = inc;
    __syncthreads();
    if (wid == 0) {
        int wv = (lane < 16) ? wsum[lane] : 0;
#pragma unroll
        for (int o = 1; o < 16; o <<= 1) {
            int t = __shfl_up_sync(0xffffffffu, wv, o);
            if (lane >= o) wv += t;
        }
        if (lane < 16) wsum[lane] = wv;
    }
    __syncthreads();
    int woff = (wid > 0) ? wsum[wid - 1] : 0;
    if (i < Nn) d_off[i] = woff + inc - v;
    if (threadIdx.x == 0) d_bsum[blockIdx.x] = wsum[15];
}

__global__ void k_scan2() {
    if (threadIdx.x != 0 || blockIdx.x != 0) return;
    int run = 0;
    for (int i = 0; i < SCAN_B; i++) { int t = d_bsum[i]; d_bsx[i] = run; run += t; }
}

__global__ void k_scan3() {
    int i = blockIdx.x * 512 + threadIdx.x;
    if (i < Nn) d_off[i] += d_bsx[blockIdx.x];
    if (i == 0) d_off[Nn] = NeT;
}

__global__ void k_scatter(const int* __restrict__ ei) {
    int e = blockIdx.x * blockDim.x + threadIdx.x;
    if (e >= NeT) return;
    int s, d;
    if (e < Ne) { s = ei[e]; d = ei[Ne + e]; } else { s = d = e - Ne; }
    float4 as = *reinterpret_cast<const float4*>(d_asrc + s * 4);
    float4 ad = *reinterpret_cast<const float4*>(d_adst + d * 4);
    float4 v;
    v.x = as.x + ad.x; v.y = as.y + ad.y; v.z = as.z + ad.z; v.w = as.w + ad.w;
    v.x = v.x > 0.f ? v.x : 0.2f * v.x;
    v.y = v.y > 0.f ? v.y : 0.2f * v.y;
    v.z = v.z > 0.f ? v.z : 0.2f * v.z;
    v.w = v.w > 0.f ? v.w : 0.2f * v.w;
    int pos = d_off[d] + atomicAdd(&d_cnt[d], 1);
    d_srcs[pos] = s;
    *reinterpret_cast<float4*>(d_escr + (size_t)pos * 4) = v;
}

// ---------------- gather3: softmax + aggregate + bias/elu/bn1 + dinv ----------------
__global__ __launch_bounds__(256) void k_gather3(const float* __restrict__ gat_b,
                                                 const float* __restrict__ g1, const float* __restrict__ b1,
                                                 const float* __restrict__ m1, const float* __restrict__ v1) {
    __shared__ float sex[8][CAP * 4];
    int w = threadIdx.x >> 5, lane = threadIdx.x & 31;
    int n = blockIdx.x * 8 + w;
    if (n >= Nn) return;
    int row = d_off[n], end = d_off[n + 1], len = end - row;

    float m0 = -1e30f, m1v = -1e30f, m2v = -1e30f, m3v = -1e30f;
    for (int base = 0; base < len; base += 32) {
        int j = base + lane;
        if (j < len) {
            float4 v = *reinterpret_cast<const float4*>(d_escr + (size_t)(row + j) * 4);
            if (j < CAP) *reinterpret_cast<float4*>(&sex[w][j * 4]) = v;
            m0 = fmaxf(m0, v.x); m1v = fmaxf(m1v, v.y); m2v = fmaxf(m2v, v.z); m3v = fmaxf(m3v, v.w);
        }
    }
#pragma unroll
    for (int o = 16; o; o >>= 1) {
        m0  = fmaxf(m0,  __shfl_xor_sync(0xffffffffu, m0,  o));
        m1v = fmaxf(m1v, __shfl_xor_sync(0xffffffffu, m1v, o));
        m2v = fmaxf(m2v, __shfl_xor_sync(0xffffffffu, m2v, o));
        m3v = fmaxf(m3v, __shfl_xor_sync(0xffffffffu, m3v, o));
    }
    float s0 = 0.f, s1 = 0.f, s2 = 0.f, s3 = 0.f;
    for (int base = 0; base < len; base += 32) {
        int j = base + lane;
        if (j < len) {
            float4 v;
            if (j < CAP) v = *reinterpret_cast<float4*>(&sex[w][j * 4]);
            else         v = *reinterpret_cast<const float4*>(d_escr + (size_t)(row + j) * 4);
            v.x = __expf(v.x - m0);  v.y = __expf(v.y - m1v);
            v.z = __expf(v.z - m2v); v.w = __expf(v.w - m3v);
            if (j < CAP) *reinterpret_cast<float4*>(&sex[w][j * 4]) = v;
            s0 += v.x; s1 += v.y; s2 += v.z; s3 += v.w;
        }
    }
#pragma unroll
    for (int o = 16; o; o >>= 1) {
        s0 += __shfl_xor_sync(0xffffffffu, s0, o);
        s1 += __shfl_xor_sync(0xffffffffu, s1, o);
        s2 += __shfl_xor_sync(0xffffffffu, s2, o);
        s3 += __shfl_xor_sync(0xffffffffu, s3, o);
    }
    float r0 = 1.0f / (s0 + 1e-16f), r1 = 1.0f / (s1 + 1e-16f);
    float r2 = 1.0f / (s2 + 1e-16f), r3 = 1.0f / (s3 + 1e-16f);

    __syncwarp();
    float a0 = 0.f, a1 = 0.f, a2 = 0.f, a3 = 0.f;
    for (int j = 0; j < len; j++) {
        int sI = d_srcs[row + j];
        float w0, w1, w2, w3;
        if (j < CAP) {
            w0 = sex[w][j * 4 + 0] * r0; w1 = sex[w][j * 4 + 1] * r1;
            w2 = sex[w][j * 4 + 2] * r2; w3 = sex[w][j * 4 + 3] * r3;
        } else {
            float4 v = *reinterpret_cast<const float4*>(d_escr + (size_t)(row + j) * 4);
            w0 = __expf(v.x - m0)  * r0; w1 = __expf(v.y - m1v) * r1;
            w2 = __expf(v.z - m2v) * r2; w3 = __expf(v.w - m3v) * r3;
        }
        const float* xs = d_xw + (size_t)sI * DIM;
        a0 += xs[lane]      * w0;
        a1 += xs[lane + 32] * w1;
        a2 += xs[lane + 64] * w2;
        a3 += xs[lane + 96] * w3;
    }
    float acc[4] = {a0, a1, a2, a3};
#pragma unroll
    for (int hd = 0; hd < 4; hd++) {
        int c = lane + 32 * hd;
        float v = acc[hd] + gat_b[c];
        v = v > 0.f ? v : (__expf(v) - 1.0f);
        v = g1[c] * (v - m1[c]) * rsqrtf(v1[c] + 1e-5f) + b1[c];
        d_h[(size_t)n * DIM + c] = v;
    }
    if (lane == 0) d_dinv[n] = rsqrtf((float)len);
}

// ---------------- GCN gemm: 8 rows/warp, 64 rows/CTA ----------------
__global__ __launch_bounds__(256) void k_gcn_gemm(const float* __restrict__ W) {
    __shared__ float sx[64][DIM];
    int tid = threadIdx.x, w = tid >> 5, lane = tid & 31;
    int base = blockIdx.x * 64;
    for (int idx = tid; idx < 64 * 32; idx += 256) {
        int rl = idx >> 5, c4 = idx & 31;
        int gr = base + rl;
        float4 v = (gr < Nn) ? reinterpret_cast<const float4*>(d_h + (size_t)gr * DIM)[c4]
                             : make_float4(0.f, 0.f, 0.f, 0.f);
        reinterpret_cast<float4*>(sx[rl])[c4] = v;
    }
    __syncthreads();
    const float4* W4 = reinterpret_cast<const float4*>(W);
    float4 acc[8];
#pragma unroll
    for (int r = 0; r < 8; r++) acc[r] = make_float4(0.f, 0.f, 0.f, 0.f);
    int rb = w * 8;
#pragma unroll 4
    for (int k = 0; k < DIM; k++) {
        float4 wv = W4[k * 32 + lane];
#pragma unroll
        for (int r = 0; r < 8; r++) {
            float xk = sx[rb + r][k];
            acc[r].x += xk * wv.x; acc[r].y += xk * wv.y;
            acc[r].z += xk * wv.z; acc[r].w += xk * wv.w;
        }
    }
#pragma unroll
    for (int r = 0; r < 8; r++) {
        int gr = base + rb + r;
        if (gr < Nn) reinterpret_cast<float4*>(d_hw + (size_t)gr * DIM)[lane] = acc[r];
    }
}

// ---------------- gather4: GCN aggregate + bias/elu/bn2 + gate ----------------
__global__ __launch_bounds__(256) void k_gather4(const float* __restrict__ gcn_b,
                                                 const float* __restrict__ g2, const float* __restrict__ b2,
                                                 const float* __restrict__ m2, const float* __restrict__ v2,
                                                 const float* __restrict__ gateW, const float* __restrict__ gate_b) {
    int lane = threadIdx.x & 31;
    int n = blockIdx.x * 8 + (threadIdx.x >> 5);
    if (n >= Nn) return;
    int row = d_off[n], end = d_off[n + 1], len = end - row;
    float dn = d_dinv[n];
    float a0 = 0.f, a1 = 0.f, a2 = 0.f, a3 = 0.f;
    for (int j = 0; j < len; j++) {
        int sI = d_srcs[row + j];
        float wgt = d_dinv[sI] * dn;
        const float* xs = d_hw + (size_t)sI * DIM;
        a0 += xs[lane]      * wgt;
        a1 += xs[lane + 32] * wgt;
        a2 += xs[lane + 64] * wgt;
        a3 += xs[lane + 96] * wgt;
    }
    float acc[4] = {a0, a1, a2, a3};
    float p = 0.f;
#pragma unroll
    for (int hd = 0; hd < 4; hd++) {
        int c = lane + 32 * hd;
        float v = acc[hd] + gcn_b[c];
        v = v > 0.f ? v : (__expf(v) - 1.0f);
        v = g2[c] * (v - m2[c]) * rsqrtf(v2[c] + 1e-5f) + b2[c];
        d_h2[(size_t)n * DIM + c] = v;
        p += v * gateW[c];
    }
#pragma unroll
    for (int o = 16; o; o >>= 1) p += __shfl_xor_sync(0xffffffffu, p, o);
    if (lane == 0) d_gate[n] = p + gate_b[0];
}

// ---------------- pooling ----------------
__global__ __launch_bounds__(128) void k_pool(const int* __restrict__ batch) {
    __shared__ int sr[2];
    __shared__ float smax[4], ssum[4];
    int b = blockIdx.x;
    int tid = threadIdx.x, lane = tid & 31, wid = tid >> 5;
    if (tid == 0) {
        int lo = 0, hi = Nn;
        while (lo < hi) { int m = (lo + hi) >> 1; if (batch[m] < b) lo = m + 1; else hi = m; }
        sr[0] = lo;
        int lo2 = lo, hi2 = Nn;
        while (lo2 < hi2) { int m = (lo2 + hi2) >> 1; if (batch[m] < b + 1) lo2 = m + 1; else hi2 = m; }
        sr[1] = lo2;
    }
    __syncthreads();
    int lo = sr[0], hi = sr[1];
    if (lo >= hi) { d_grep[(size_t)b * DIM + tid] = 0.f; return; }
    float mv = -1e30f;
    for (int n = lo + tid; n < hi; n += 128) mv = fmaxf(mv, d_gate[n]);
#pragma unroll
    for (int o = 16; o; o >>= 1) mv = fmaxf(mv, __shfl_xor_sync(0xffffffffu, mv, o));
    if (lane == 0) smax[wid] = mv;
    __syncthreads();
    mv = fmaxf(fmaxf(smax[0], smax[1]), fmaxf(smax[2], smax[3]));
    float sv = 0.f;
    for (int n = lo + tid; n < hi; n += 128) sv += __expf(d_gate[n] - mv);
#pragma unroll
    for (int o = 16; o; o >>= 1) sv += __shfl_xor_sync(0xffffffffu, sv, o);
    if (lane == 0) ssum[wid] = sv;
    __syncthreads();
    sv = ssum[0] + ssum[1] + ssum[2] + ssum[3];
    float rcp = 1.0f / (sv + 1e-16f);
    float acc = 0.f;
    for (int n = lo; n < hi; n++) {
        float wn = __expf(d_gate[n] - mv) * rcp;
        acc += wn * d_h2[(size_t)n * DIM + tid];
    }
    d_grep[(size_t)b * DIM + tid] = acc;
}

// ---------------- LSTM input projection: xpre[b][t][j] ----------------
__global__ void k_xpre(const float* __restrict__ quant, const float* __restrict__ Wih,
                       const float* __restrict__ bih, const float* __restrict__ bhh) {
    __shared__ float4 sq[32][8];
    int t = blockIdx.x;
    int bbase = blockIdx.y * 32;
    int tid = threadIdx.x;  // 512
    for (int i = tid; i < 32 * 8; i += 512) {
        int b = i >> 3, k = i & 7;
        sq[b][k] = reinterpret_cast<const float4*>(quant + ((size_t)(bbase + b) * Tt + t) * QD)[k];
    }
    __syncthreads();
    int j = tid;
    float wr[QD];
#pragma unroll
    for (int k = 0; k < QD; k++) wr[k] = Wih[j * QD + k];
    float bs = bih[j] + bhh[j];
    for (int b = 0; b < 32; b++) {
        float acc = bs;
#pragma unroll
        for (int k8 = 0; k8 < 8; k8++) {
            float4 q = sq[b][k8];
            acc += q.x * wr[k8 * 4] + q.y * wr[k8 * 4 + 1] + q.z * wr[k8 * 4 + 2] + q.w * wr[k8 * 4 + 3];
        }
        d_xpre[((size_t)(bbase + b) * Tt + t) * 512 + j] = acc;
    }
}

// ---------------- persistent LSTM ----------------
__global__ __launch_bounds__(512) void k_lstm_persist(const float* __restrict__ Whh) {
    extern __shared__ float dyn[];
    float* s_w    = dyn;                         // [512][68]
    float* s_h    = dyn + SW_FLOATS;             // [BPC][128]
    float* s_gate = dyn + SW_FLOATS + SH_FLOATS; // [BPC][512]
    int j = threadIdx.x;

    float4 w4[16];
    const float4* Wr = reinterpret_cast<const float4*>(Whh + (size_t)j * 128);
#pragma unroll
    for (int q = 0; q < 16; q++) w4[q] = Wr[q];
#pragma unroll
    for (int q = 0; q < 16; q++) {
        float4 v = Wr[16 + q];
        *reinterpret_cast<float4*>(&s_w[j * 68 + q * 4]) = v;
    }
    if (j < BPC * 128) s_h[j] = 0.f;
    float c0 = 0.f, c1 = 0.f;
    __syncthreads();

    int bglob = blockIdx.x * BPC;
    const float* xp0 = d_xpre + (size_t)(bglob + 0) * Tt * 512;
    const float* xp1 = d_xpre + (size_t)(bglob + 1) * Tt * 512;

    for (int t = 0; t < Tt; t++) {
        float x0 = xp0[t * 512 + j];
        float x1 = xp1[t * 512 + j];
        float a0 = 0.f, a1 = 0.f;
#pragma unroll
        for (int q = 0; q < 16; q++) {
            float4 h0 = *reinterpret_cast<const float4*>(&s_h[0 * 128 + q * 4]);
            float4 h1 = *reinterpret_cast<const float4*>(&s_h[1 * 128 + q * 4]);
            float4 wv = w4[q];
            a0 += wv.x * h0.x + wv.y * h0.y + wv.z * h0.z + wv.w * h0.w;
            a1 += wv.x * h1.x + wv.y * h1.y + wv.z * h1.z + wv.w * h1.w;
        }
#pragma unroll
        for (int q = 0; q < 16; q++) {
            float4 wv = *reinterpret_cast<const float4*>(&s_w[j * 68 + q * 4]);
            float4 h0 = *reinterpret_cast<const float4*>(&s_h[0 * 128 + 64 + q * 4]);
            float4 h1 = *reinterpret_cast<const float4*>(&s_h[1 * 128 + 64 + q * 4]);
            a0 += wv.x * h0.x + wv.y * h0.y + wv.z * h0.z + wv.w * h0.w;
            a1 += wv.x * h1.x + wv.y * h1.y + wv.z * h1.z + wv.w * h1.w;
        }
        s_gate[0 * 512 + j] = a0 + x0;
        s_gate[1 * 512 + j] = a1 + x1;
        __syncthreads();
        if (j < 256) {
            int b = j >> 7, u = j & 127;
            float gi = s_gate[b * 512 + u];
            float gf = s_gate[b * 512 + 128 + u];
            float gg = s_gate[b * 512 + 256 + u];
            float go = s_gate[b * 512 + 384 + u];
            float cv = (j < 128) ? c0 : c1;
            cv = sigf(gf) * cv + sigf(gi) * tanhf(gg);
            if (j < 128) c0 = cv; else c1 = cv;
            s_h[b * 128 + u] = sigf(go) * tanhf(cv);
        }
        __syncthreads();
    }
    if (j < BPC * 128) {
        int b = j >> 7, u = j & 127;
        d_hT[u * Bb + (bglob + b)] = s_h[b * 128 + u];
    }
}

// ---------------- final linear ----------------
__global__ void k_final(const float* __restrict__ fcW, const float* __restrict__ fcb,
                        float* __restrict__ out) {
    int b = threadIdx.x;  // 256
    float acc = fcb[0];
#pragma unroll 4
    for (int c = 0; c < DIM; c++) acc += d_grep[b * DIM + c] * fcW[c];
#pragma unroll 4
    for (int u = 0; u < LH; u++) acc += d_hT[u * Bb + b] * fcW[DIM + u];
    out[b] = acc;
}

// ---------------- launch ----------------
extern "C" void kernel_launch(void* const* d_in, const int* in_sizes, int n_in,
                              void* d_out, int out_size) {
    (void)in_sizes; (void)n_in; (void)out_size;
    const float* x       = (const float*)d_in[0];
    const int*   ei      = (const int*)d_in[1];
    const int*   batch   = (const int*)d_in[2];
    const float* quant   = (const float*)d_in[3];
    const float* gat_W   = (const float*)d_in[4];
    const float* att_src = (const float*)d_in[5];
    const float* att_dst = (const float*)d_in[6];
    const float* gat_b   = (const float*)d_in[7];
    const float* bn1_g   = (const float*)d_in[8];
    const float* bn1_b   = (const float*)d_in[9];
    const float* bn1_m   = (const float*)d_in[10];
    const float* bn1_v   = (const float*)d_in[11];
    const float* gcn_W   = (const float*)d_in[12];
    const float* gcn_b   = (const float*)d_in[13];
    const float* bn2_g   = (const float*)d_in[14];
    const float* bn2_b   = (const float*)d_in[15];
    const float* bn2_m   = (const float*)d_in[16];
    const float* bn2_v   = (const float*)d_in[17];
    const float* gate_W  = (const float*)d_in[18];
    const float* gate_b  = (const float*)d_in[19];
    const float* Wih     = (const float*)d_in[20];
    const float* Whh     = (const float*)d_in[21];
    const float* bih     = (const float*)d_in[22];
    const float* bhh     = (const float*)d_in[23];
    const float* fcW     = (const float*)d_in[24];
    const float* fcb     = (const float*)d_in[25];
    float* out = (float*)d_out;

    static cudaStream_t s_lstm = nullptr, s_csr = nullptr;
    static cudaEvent_t evA = nullptr, evB = nullptr, evC = nullptr, evD = nullptr;
    if (s_lstm == nullptr) {
        cudaStreamCreateWithFlags(&s_lstm, cudaStreamNonBlocking);
        cudaStreamCreateWithFlags(&s_csr, cudaStreamNonBlocking);
        cudaEventCreateWithFlags(&evA, cudaEventDisableTiming);
        cudaEventCreateWithFlags(&evB, cudaEventDisableTiming);
        cudaEventCreateWithFlags(&evC, cudaEventDisableTiming);
        cudaEventCreateWithFlags(&evD, cudaEventDisableTiming);
        cudaFuncSetAttribute(k_lstm_persist, cudaFuncAttributeMaxDynamicSharedMemorySize, LSTM_SMEM_BYTES);
        cudaFuncSetAttribute(k_lstm_persist, cudaFuncAttributePreferredSharedMemoryCarveout, 100);
    }

    // fork: LSTM branch on side stream
    cudaEventRecord(evA, 0);
    cudaStreamWaitEvent(s_lstm, evA, 0);
    k_xpre<<<dim3(Tt, Bb / 32), 512, 0, s_lstm>>>(quant, Wih, bih, bhh);
    k_lstm_persist<<<LCTAS, 512, LSTM_SMEM_BYTES, s_lstm>>>(Whh);
    cudaEventRecord(evB, s_lstm);

    // fork: CSR build (needs only edge_index) overlaps with gat_gemm
    cudaEventRecord(evC, 0);
    cudaStreamWaitEvent(s_csr, evC, 0);
    k_init<<<(Nn + 511) / 512, 512, 0, s_csr>>>();
    k_count<<<(NeT + 255) / 256, 256, 0, s_csr>>>(ei);
    k_scan1<<<SCAN_B, 512, 0, s_csr>>>();
    k_scan2<<<1, 32, 0, s_csr>>>();
    k_scan3<<<SCAN_B, 512, 0, s_csr>>>();
    cudaEventRecord(evD, s_csr);

    // graph branch on main stream
    k_gat_gemm<<<(Nn + 63) / 64, 256>>>(x, gat_W, att_src, att_dst);
    cudaStreamWaitEvent(0, evD, 0);
    k_scatter<<<(NeT + 255) / 256, 256>>>(ei);
    k_gather3<<<(Nn + 7) / 8, 256>>>(gat_b, bn1_g, bn1_b, bn1_m, bn1_v);
    k_gcn_gemm<<<(Nn + 63) / 64, 256>>>(gcn_W);
    k_gather4<<<(Nn + 7) / 8, 256>>>(gcn_b, bn2_g, bn2_b, bn2_m, bn2_v, gate_W, gate_b);
    k_pool<<<Bb, 128>>>(batch);

    // join
    cudaStreamWaitEvent(0, evB, 0);
    k_final<<<1, 256>>>(fcW, fcb, out);
}

// round 6
// speedup vs baseline: 2.7242x; 1.0341x over previous
#include <cuda_runtime.h>
#include <math.h>

// ---------------- problem constants ----------------
constexpr int Nn  = 50000;     // nodes
constexpr int Ne  = 800000;    // edges (without self loops)
constexpr int NeT = 850000;    // edges + self loops
constexpr int Bb  = 256;       // graphs / batch
constexpr int Tt  = 50;        // timesteps
constexpr int DIM = 128;       // feature dim
constexpr int LH  = 128;       // lstm hidden
constexpr int QD  = 32;        // lstm input dim
constexpr int CAP = 64;        // per-row smem edge cache
constexpr int SCAN_B = (Nn + 511) / 512;   // 98
constexpr int LCTAS = 128;     // persistent LSTM CTAs
constexpr int BPC = Bb / LCTAS; // 2 batches per CTA

constexpr int SW_FLOATS = 512 * 68;
constexpr int SH_FLOATS = BPC * 128;
constexpr int SG_FLOATS = BPC * 512;
constexpr int LSTM_SMEM_BYTES = (SW_FLOATS + SH_FLOATS + SG_FLOATS) * 4;

// ---------------- device scratch ----------------
__device__ float    d_xw[Nn * DIM];
__device__ float    d_asrc[Nn * 4];
__device__ float    d_adst[Nn * 4];
__device__ int      d_degi[Nn];
__device__ int      d_cnt[Nn];
__device__ int      d_off[Nn + 1];
__device__ int      d_bsum[SCAN_B];
__device__ int      d_bsx[SCAN_B];
__device__ int      d_srcs[NeT];
__device__ float    d_h[Nn * DIM];
__device__ float    d_dinv[Nn];
__device__ float    d_hw[Nn * DIM];
__device__ float    d_h2[Nn * DIM];
__device__ float    d_gate[Nn];
__device__ float    d_grep[Bb * DIM];
__device__ float    d_xpre[Bb * Tt * 4 * LH];
__device__ float    d_hT[LH * Bb];

__device__ __forceinline__ float sigf(float x) { return 1.0f / (1.0f + __expf(-x)); }
__device__ __forceinline__ float lrelu(float x) { return x > 0.f ? x : 0.2f * x; }

// ---------------- init ----------------
__global__ void k_init() {
    int i = blockIdx.x * blockDim.x + threadIdx.x;
    if (i < Nn) { d_degi[i] = 0; d_cnt[i] = 0; }
}

// ---------------- GAT gemm: 8 rows/warp, 64 rows/CTA ----------------
__global__ __launch_bounds__(256) void k_gat_gemm(const float* __restrict__ x, const float* __restrict__ W,
                                                  const float* __restrict__ att_s, const float* __restrict__ att_d) {
    __shared__ float sx[64][DIM];
    int tid = threadIdx.x, w = tid >> 5, lane = tid & 31;
    int base = blockIdx.x * 64;
    for (int idx = tid; idx < 64 * 32; idx += 256) {
        int rl = idx >> 5, c4 = idx & 31;
        int gr = base + rl;
        float4 v = (gr < Nn) ? reinterpret_cast<const float4*>(x + (size_t)gr * DIM)[c4]
                             : make_float4(0.f, 0.f, 0.f, 0.f);
        reinterpret_cast<float4*>(sx[rl])[c4] = v;
    }
    __syncthreads();
    const float4* W4 = reinterpret_cast<const float4*>(W);
    float4 acc[8];
#pragma unroll
    for (int r = 0; r < 8; r++) acc[r] = make_float4(0.f, 0.f, 0.f, 0.f);
    int rb = w * 8;
#pragma unroll 4
    for (int k = 0; k < DIM; k++) {
        float4 wv = W4[k * 32 + lane];
#pragma unroll
        for (int r = 0; r < 8; r++) {
            float xk = sx[rb + r][k];
            acc[r].x += xk * wv.x; acc[r].y += xk * wv.y;
            acc[r].z += xk * wv.z; acc[r].w += xk * wv.w;
        }
    }
    int c0 = lane * 4;
    float s0 = att_s[c0], s1 = att_s[c0 + 1], s2 = att_s[c0 + 2], s3 = att_s[c0 + 3];
    float d0 = att_d[c0], d1 = att_d[c0 + 1], d2 = att_d[c0 + 2], d3 = att_d[c0 + 3];
#pragma unroll
    for (int r = 0; r < 8; r++) {
        int gr = base + rb + r;
        if (gr >= Nn) break;
        reinterpret_cast<float4*>(d_xw + (size_t)gr * DIM)[lane] = acc[r];
        float ps = acc[r].x * s0 + acc[r].y * s1 + acc[r].z * s2 + acc[r].w * s3;
        float pd = acc[r].x * d0 + acc[r].y * d1 + acc[r].z * d2 + acc[r].w * d3;
#pragma unroll
        for (int off = 4; off; off >>= 1) {
            ps += __shfl_xor_sync(0xffffffffu, ps, off);
            pd += __shfl_xor_sync(0xffffffffu, pd, off);
        }
        if ((lane & 7) == 0) {
            int h = lane >> 3;
            d_asrc[gr * 4 + h] = ps;
            d_adst[gr * 4 + h] = pd;
        }
    }
}

// ---------------- CSR build ----------------
__global__ void k_count(const int* __restrict__ ei) {
    int e = blockIdx.x * blockDim.x + threadIdx.x;
    if (e >= NeT) return;
    int d = (e < Ne) ? ei[Ne + e] : e - Ne;
    atomicAdd(&d_degi[d], 1);
}

__global__ void k_scan1() {
    __shared__ int wsum[16];
    int i = blockIdx.x * 512 + threadIdx.x;
    int v = (i < Nn) ? d_degi[i] : 0;
    int lane = threadIdx.x & 31, wid = threadIdx.x >> 5;
    int inc = v;
#pragma unroll
    for (int o = 1; o < 32; o <<= 1) {
        int t = __shfl_up_sync(0xffffffffu, inc, o);
        if (lane >= o) inc += t;
    }
    if (lane == 31) wsum[wid] = inc;
    __syncthreads();
    if (wid == 0) {
        int wv = (lane < 16) ? wsum[lane] : 0;
#pragma unroll
        for (int o = 1; o < 16; o <<= 1) {
            int t = __shfl_up_sync(0xffffffffu, wv, o);
            if (lane >= o) wv += t;
        }
        if (lane < 16) wsum[lane] = wv;
    }
    __syncthreads();
    int woff = (wid > 0) ? wsum[wid - 1] : 0;
    if (i < Nn) d_off[i] = woff + inc - v;
    if (threadIdx.x == 0) d_bsum[blockIdx.x] = wsum[15];
}

__global__ void k_scan2() {
    if (threadIdx.x != 0 || blockIdx.x != 0) return;
    int run = 0;
    for (int i = 0; i < SCAN_B; i++) { int t = d_bsum[i]; d_bsx[i] = run; run += t; }
}

__global__ void k_scan3() {
    int i = blockIdx.x * 512 + threadIdx.x;
    if (i < Nn) d_off[i] += d_bsx[blockIdx.x];
    if (i == 0) d_off[Nn] = NeT;
}

// scatter: index-only CSR fill
__global__ void k_scatter(const int* __restrict__ ei) {
    int e = blockIdx.x * blockDim.x + threadIdx.x;
    if (e >= NeT) return;
    int s, d;
    if (e < Ne) { s = ei[e]; d = ei[Ne + e]; } else { s = d = e - Ne; }
    int pos = d_off[d] + atomicAdd(&d_cnt[d], 1);
    d_srcs[pos] = s;
}

// ---------------- gather3: score recompute + softmax + aggregate + bias/elu/bn1 ----------------
__global__ __launch_bounds__(256) void k_gather3(const float* __restrict__ gat_b,
                                                 const float* __restrict__ g1, const float* __restrict__ b1,
                                                 const float* __restrict__ m1, const float* __restrict__ v1) {
    __shared__ float sex[8][CAP * 4];   // cached scores (then exp'd weights)
    __shared__ int   ssrc[8][CAP];      // cached src indices
    int w = threadIdx.x >> 5, lane = threadIdx.x & 31;
    int n = blockIdx.x * 8 + w;
    if (n >= Nn) return;
    int row = d_off[n], end = d_off[n + 1], len = end - row;
    float4 ad = *reinterpret_cast<const float4*>(d_adst + n * 4);   // warp-uniform

    // A1: gather asrc, compute leaky scores, cache, max-reduce
    float m0 = -1e30f, m1v = -1e30f, m2v = -1e30f, m3v = -1e30f;
    for (int base = 0; base < len; base += 32) {
        int j = base + lane;
        if (j < len) {
            int s = d_srcs[row + j];
            float4 as = *reinterpret_cast<const float4*>(d_asrc + s * 4);
            float4 v;
            v.x = lrelu(as.x + ad.x); v.y = lrelu(as.y + ad.y);
            v.z = lrelu(as.z + ad.z); v.w = lrelu(as.w + ad.w);
            if (j < CAP) { *reinterpret_cast<float4*>(&sex[w][j * 4]) = v; ssrc[w][j] = s; }
            m0 = fmaxf(m0, v.x); m1v = fmaxf(m1v, v.y); m2v = fmaxf(m2v, v.z); m3v = fmaxf(m3v, v.w);
        }
    }
#pragma unroll
    for (int o = 16; o; o >>= 1) {
        m0  = fmaxf(m0,  __shfl_xor_sync(0xffffffffu, m0,  o));
        m1v = fmaxf(m1v, __shfl_xor_sync(0xffffffffu, m1v, o));
        m2v = fmaxf(m2v, __shfl_xor_sync(0xffffffffu, m2v, o));
        m3v = fmaxf(m3v, __shfl_xor_sync(0xffffffffu, m3v, o));
    }
    // A2: exp + sum (cached region + recompute fallback)
    float s0 = 0.f, s1 = 0.f, s2 = 0.f, s3 = 0.f;
    for (int base = 0; base < len; base += 32) {
        int j = base + lane;
        if (j < len) {
            float4 v;
            if (j < CAP) v = *reinterpret_cast<float4*>(&sex[w][j * 4]);
            else {
                int s = d_srcs[row + j];
                float4 as = *reinterpret_cast<const float4*>(d_asrc + s * 4);
                v.x = lrelu(as.x + ad.x); v.y = lrelu(as.y + ad.y);
                v.z = lrelu(as.z + ad.z); v.w = lrelu(as.w + ad.w);
            }
            v.x = __expf(v.x - m0);  v.y = __expf(v.y - m1v);
            v.z = __expf(v.z - m2v); v.w = __expf(v.w - m3v);
            if (j < CAP) *reinterpret_cast<float4*>(&sex[w][j * 4]) = v;
            s0 += v.x; s1 += v.y; s2 += v.z; s3 += v.w;
        }
    }
#pragma unroll
    for (int o = 16; o; o >>= 1) {
        s0 += __shfl_xor_sync(0xffffffffu, s0, o);
        s1 += __shfl_xor_sync(0xffffffffu, s1, o);
        s2 += __shfl_xor_sync(0xffffffffu, s2, o);
        s3 += __shfl_xor_sync(0xffffffffu, s3, o);
    }
    float r0 = 1.0f / (s0 + 1e-16f), r1 = 1.0f / (s1 + 1e-16f);
    float r2 = 1.0f / (s2 + 1e-16f), r3 = 1.0f / (s3 + 1e-16f);

    __syncwarp();
    // B: aggregate, unrolled by 2 for MLP
    float a0 = 0.f, a1 = 0.f, a2 = 0.f, a3 = 0.f;
    int jmax = len < CAP ? len : CAP;
    int j = 0;
    for (; j + 2 <= jmax; j += 2) {
        int sA = ssrc[w][j], sB = ssrc[w][j + 1];
        float wA0 = sex[w][j * 4 + 0] * r0, wA1 = sex[w][j * 4 + 1] * r1;
        float wA2 = sex[w][j * 4 + 2] * r2, wA3 = sex[w][j * 4 + 3] * r3;
        float wB0 = sex[w][j * 4 + 4] * r0, wB1 = sex[w][j * 4 + 5] * r1;
        float wB2 = sex[w][j * 4 + 6] * r2, wB3 = sex[w][j * 4 + 7] * r3;
        const float* xA = d_xw + (size_t)sA * DIM;
        const float* xB = d_xw + (size_t)sB * DIM;
        float A0 = xA[lane],      A1 = xA[lane + 32], A2 = xA[lane + 64], A3 = xA[lane + 96];
        float B0 = xB[lane],      B1 = xB[lane + 32], B2 = xB[lane + 64], B3 = xB[lane + 96];
        a0 += A0 * wA0 + B0 * wB0;
        a1 += A1 * wA1 + B1 * wB1;
        a2 += A2 * wA2 + B2 * wB2;
        a3 += A3 * wA3 + B3 * wB3;
    }
    for (; j < jmax; j++) {
        int sI = ssrc[w][j];
        const float* xs = d_xw + (size_t)sI * DIM;
        a0 += xs[lane]      * (sex[w][j * 4 + 0] * r0);
        a1 += xs[lane + 32] * (sex[w][j * 4 + 1] * r1);
        a2 += xs[lane + 64] * (sex[w][j * 4 + 2] * r2);
        a3 += xs[lane + 96] * (sex[w][j * 4 + 3] * r3);
    }
    for (; j < len; j++) {      // rare fallback beyond CAP
        int sI = d_srcs[row + j];
        float4 as = *reinterpret_cast<const float4*>(d_asrc + sI * 4);
        float w0 = __expf(lrelu(as.x + ad.x) - m0)  * r0;
        float w1 = __expf(lrelu(as.y + ad.y) - m1v) * r1;
        float w2 = __expf(lrelu(as.z + ad.z) - m2v) * r2;
        float w3 = __expf(lrelu(as.w + ad.w) - m3v) * r3;
        const float* xs = d_xw + (size_t)sI * DIM;
        a0 += xs[lane]      * w0;
        a1 += xs[lane + 32] * w1;
        a2 += xs[lane + 64] * w2;
        a3 += xs[lane + 96] * w3;
    }
    float acc[4] = {a0, a1, a2, a3};
#pragma unroll
    for (int hd = 0; hd < 4; hd++) {
        int c = lane + 32 * hd;
        float v = acc[hd] + gat_b[c];
        v = v > 0.f ? v : (__expf(v) - 1.0f);
        v = g1[c] * (v - m1[c]) * rsqrtf(v1[c] + 1e-5f) + b1[c];
        d_h[(size_t)n * DIM + c] = v;
    }
    if (lane == 0) d_dinv[n] = rsqrtf((float)len);
}

// ---------------- GCN gemm: 8 rows/warp ----------------
__global__ __launch_bounds__(256) void k_gcn_gemm(const float* __restrict__ W) {
    __shared__ float sx[64][DIM];
    int tid = threadIdx.x, w = tid >> 5, lane = tid & 31;
    int base = blockIdx.x * 64;
    for (int idx = tid; idx < 64 * 32; idx += 256) {
        int rl = idx >> 5, c4 = idx & 31;
        int gr = base + rl;
        float4 v = (gr < Nn) ? reinterpret_cast<const float4*>(d_h + (size_t)gr * DIM)[c4]
                             : make_float4(0.f, 0.f, 0.f, 0.f);
        reinterpret_cast<float4*>(sx[rl])[c4] = v;
    }
    __syncthreads();
    const float4* W4 = reinterpret_cast<const float4*>(W);
    float4 acc[8];
#pragma unroll
    for (int r = 0; r < 8; r++) acc[r] = make_float4(0.f, 0.f, 0.f, 0.f);
    int rb = w * 8;
#pragma unroll 4
    for (int k = 0; k < DIM; k++) {
        float4 wv = W4[k * 32 + lane];
#pragma unroll
        for (int r = 0; r < 8; r++) {
            float xk = sx[rb + r][k];
            acc[r].x += xk * wv.x; acc[r].y += xk * wv.y;
            acc[r].z += xk * wv.z; acc[r].w += xk * wv.w;
        }
    }
#pragma unroll
    for (int r = 0; r < 8; r++) {
        int gr = base + rb + r;
        if (gr < Nn) reinterpret_cast<float4*>(d_hw + (size_t)gr * DIM)[lane] = acc[r];
    }
}

// ---------------- gather4: GCN aggregate + bias/elu/bn2 + gate ----------------
__global__ __launch_bounds__(256) void k_gather4(const float* __restrict__ gcn_b,
                                                 const float* __restrict__ g2, const float* __restrict__ b2,
                                                 const float* __restrict__ m2, const float* __restrict__ v2,
                                                 const float* __restrict__ gateW, const float* __restrict__ gate_b) {
    int lane = threadIdx.x & 31;
    int n = blockIdx.x * 8 + (threadIdx.x >> 5);
    if (n >= Nn) return;
    int row = d_off[n], end = d_off[n + 1];
    float dn = d_dinv[n];
    float a0 = 0.f, a1 = 0.f, a2 = 0.f, a3 = 0.f;
    int j = row;
    for (; j + 2 <= end; j += 2) {
        int sA = d_srcs[j], sB = d_srcs[j + 1];
        float wA = d_dinv[sA] * dn, wB = d_dinv[sB] * dn;
        const float* xA = d_hw + (size_t)sA * DIM;
        const float* xB = d_hw + (size_t)sB * DIM;
        float A0 = xA[lane],      A1 = xA[lane + 32], A2 = xA[lane + 64], A3 = xA[lane + 96];
        float B0 = xB[lane],      B1 = xB[lane + 32], B2 = xB[lane + 64], B3 = xB[lane + 96];
        a0 += A0 * wA + B0 * wB;
        a1 += A1 * wA + B1 * wB;
        a2 += A2 * wA + B2 * wB;
        a3 += A3 * wA + B3 * wB;
    }
    for (; j < end; j++) {
        int sI = d_srcs[j];
        float wgt = d_dinv[sI] * dn;
        const float* xs = d_hw + (size_t)sI * DIM;
        a0 += xs[lane]      * wgt;
        a1 += xs[lane + 32] * wgt;
        a2 += xs[lane + 64] * wgt;
        a3 += xs[lane + 96] * wgt;
    }
    float acc[4] = {a0, a1, a2, a3};
    float p = 0.f;
#pragma unroll
    for (int hd = 0; hd < 4; hd++) {
        int c = lane + 32 * hd;
        float v = acc[hd] + gcn_b[c];
        v = v > 0.f ? v : (__expf(v) - 1.0f);
        v = g2[c] * (v - m2[c]) * rsqrtf(v2[c] + 1e-5f) + b2[c];
        d_h2[(size_t)n * DIM + c] = v;
        p += v * gateW[c];
    }
#pragma unroll
    for (int o = 16; o; o >>= 1) p += __shfl_xor_sync(0xffffffffu, p, o);
    if (lane == 0) d_gate[n] = p + gate_b[0];
}

// ---------------- pooling ----------------
__global__ __launch_bounds__(128) void k_pool(const int* __restrict__ batch) {
    __shared__ int sr[2];
    __shared__ float smax[4], ssum[4];
    int b = blockIdx.x;
    int tid = threadIdx.x, lane = tid & 31, wid = tid >> 5;
    if (tid == 0) {
        int lo = 0, hi = Nn;
        while (lo < hi) { int m = (lo + hi) >> 1; if (batch[m] < b) lo = m + 1; else hi = m; }
        sr[0] = lo;
        int lo2 = lo, hi2 = Nn;
        while (lo2 < hi2) { int m = (lo2 + hi2) >> 1; if (batch[m] < b + 1) lo2 = m + 1; else hi2 = m; }
        sr[1] = lo2;
    }
    __syncthreads();
    int lo = sr[0], hi = sr[1];
    if (lo >= hi) { d_grep[(size_t)b * DIM + tid] = 0.f; return; }
    float mv = -1e30f;
    for (int n = lo + tid; n < hi; n += 128) mv = fmaxf(mv, d_gate[n]);
#pragma unroll
    for (int o = 16; o; o >>= 1) mv = fmaxf(mv, __shfl_xor_sync(0xffffffffu, mv, o));
    if (lane == 0) smax[wid] = mv;
    __syncthreads();
    mv = fmaxf(fmaxf(smax[0], smax[1]), fmaxf(smax[2], smax[3]));
    float sv = 0.f;
    for (int n = lo + tid; n < hi; n += 128) sv += __expf(d_gate[n] - mv);
#pragma unroll
    for (int o = 16; o; o >>= 1) sv += __shfl_xor_sync(0xffffffffu, sv, o);
    if (lane == 0) ssum[wid] = sv;
    __syncthreads();
    sv = ssum[0] + ssum[1] + ssum[2] + ssum[3];
    float rcp = 1.0f / (sv + 1e-16f);
    float acc = 0.f;
    int n = lo;
    for (; n + 2 <= hi; n += 2) {
        float wA = __expf(d_gate[n] - mv) * rcp;
        float wB = __expf(d_gate[n + 1] - mv) * rcp;
        float hA = d_h2[(size_t)n * DIM + tid];
        float hB = d_h2[(size_t)(n + 1) * DIM + tid];
        acc += wA * hA + wB * hB;
    }
    if (n < hi) acc += __expf(d_gate[n] - mv) * rcp * d_h2[(size_t)n * DIM + tid];
    d_grep[(size_t)b * DIM + tid] = acc;
}

// ---------------- LSTM input projection ----------------
__global__ void k_xpre(const float* __restrict__ quant, const float* __restrict__ Wih,
                       const float* __restrict__ bih, const float* __restrict__ bhh) {
    __shared__ float4 sq[32][8];
    int t = blockIdx.x;
    int bbase = blockIdx.y * 32;
    int tid = threadIdx.x;  // 512
    for (int i = tid; i < 32 * 8; i += 512) {
        int b = i >> 3, k = i & 7;
        sq[b][k] = reinterpret_cast<const float4*>(quant + ((size_t)(bbase + b) * Tt + t) * QD)[k];
    }
    __syncthreads();
    int j = tid;
    float wr[QD];
#pragma unroll
    for (int k = 0; k < QD; k++) wr[k] = Wih[j * QD + k];
    float bs = bih[j] + bhh[j];
    for (int b = 0; b < 32; b++) {
        float acc = bs;
#pragma unroll
        for (int k8 = 0; k8 < 8; k8++) {
            float4 q = sq[b][k8];
            acc += q.x * wr[k8 * 4] + q.y * wr[k8 * 4 + 1] + q.z * wr[k8 * 4 + 2] + q.w * wr[k8 * 4 + 3];
        }
        d_xpre[((size_t)(bbase + b) * Tt + t) * 512 + j] = acc;
    }
}

// ---------------- persistent LSTM ----------------
__global__ __launch_bounds__(512) void k_lstm_persist(const float* __restrict__ Whh) {
    extern __shared__ float dyn[];
    float* s_w    = dyn;
    float* s_h    = dyn + SW_FLOATS;
    float* s_gate = dyn + SW_FLOATS + SH_FLOATS;
    int j = threadIdx.x;

    float4 w4[16];
    const float4* Wr = reinterpret_cast<const float4*>(Whh + (size_t)j * 128);
#pragma unroll
    for (int q = 0; q < 16; q++) w4[q] = Wr[q];
#pragma unroll
    for (int q = 0; q < 16; q++) {
        float4 v = Wr[16 + q];
        *reinterpret_cast<float4*>(&s_w[j * 68 + q * 4]) = v;
    }
    if (j < BPC * 128) s_h[j] = 0.f;
    float c0 = 0.f, c1 = 0.f;
    __syncthreads();

    int bglob = blockIdx.x * BPC;
    const float* xp0 = d_xpre + (size_t)(bglob + 0) * Tt * 512;
    const float* xp1 = d_xpre + (size_t)(bglob + 1) * Tt * 512;

    for (int t = 0; t < Tt; t++) {
        float x0 = xp0[t * 512 + j];
        float x1 = xp1[t * 512 + j];
        float a0 = 0.f, a1 = 0.f;
#pragma unroll
        for (int q = 0; q < 16; q++) {
            float4 h0 = *reinterpret_cast<const float4*>(&s_h[0 * 128 + q * 4]);
            float4 h1 = *reinterpret_cast<const float4*>(&s_h[1 * 128 + q * 4]);
            float4 wv = w4[q];
            a0 += wv.x * h0.x + wv.y * h0.y + wv.z * h0.z + wv.w * h0.w;
            a1 += wv.x * h1.x + wv.y * h1.y + wv.z * h1.z + wv.w * h1.w;
        }
#pragma unroll
        for (int q = 0; q < 16; q++) {
            float4 wv = *reinterpret_cast<const float4*>(&s_w[j * 68 + q * 4]);
            float4 h0 = *reinterpret_cast<const float4*>(&s_h[0 * 128 + 64 + q * 4]);
            float4 h1 = *reinterpret_cast<const float4*>(&s_h[1 * 128 + 64 + q * 4]);
            a0 += wv.x * h0.x + wv.y * h0.y + wv.z * h0.z + wv.w * h0.w;
            a1 += wv.x * h1.x + wv.y * h1.y + wv.z * h1.z + wv.w * h1.w;
        }
        s_gate[0 * 512 + j] = a0 + x0;
        s_gate[1 * 512 + j] = a1 + x1;
        __syncthreads();
        if (j < 256) {
            int b = j >> 7, u = j & 127;
            float gi = s_gate[b * 512 + u];
            float gf = s_gate[b * 512 + 128 + u];
            float gg = s_gate[b * 512 + 256 + u];
            float go = s_gate[b * 512 + 384 + u];
            float cv = (j < 128) ? c0 : c1;
            cv = sigf(gf) * cv + sigf(gi) * tanhf(gg);
            if (j < 128) c0 = cv; else c1 = cv;
            s_h[b * 128 + u] = sigf(go) * tanhf(cv);
        }
        __syncthreads();
    }
    if (j < BPC * 128) {
        int b = j >> 7, u = j & 127;
        d_hT[u * Bb + (bglob + b)] = s_h[b * 128 + u];
    }
}

// ---------------- final linear ----------------
__global__ void k_final(const float* __restrict__ fcW, const float* __restrict__ fcb,
                        float* __restrict__ out) {
    int b = threadIdx.x;  // 256
    float acc = fcb[0];
#pragma unroll 4
    for (int c = 0; c < DIM; c++) acc += d_grep[b * DIM + c] * fcW[c];
#pragma unroll 4
    for (int u = 0; u < LH; u++) acc += d_hT[u * Bb + b] * fcW[DIM + u];
    out[b] = acc;
}

// ---------------- launch ----------------
extern "C" void kernel_launch(void* const* d_in, const int* in_sizes, int n_in,
                              void* d_out, int out_size) {
    (void)in_sizes; (void)n_in; (void)out_size;
    const float* x       = (const float*)d_in[0];
    const int*   ei      = (const int*)d_in[1];
    const int*   batch   = (const int*)d_in[2];
    const float* quant   = (const float*)d_in[3];
    const float* gat_W   = (const float*)d_in[4];
    const float* att_src = (const float*)d_in[5];
    const float* att_dst = (const float*)d_in[6];
    const float* gat_b   = (const float*)d_in[7];
    const float* bn1_g   = (const float*)d_in[8];
    const float* bn1_b   = (const float*)d_in[9];
    const float* bn1_m   = (const float*)d_in[10];
    const float* bn1_v   = (const float*)d_in[11];
    const float* gcn_W   = (const float*)d_in[12];
    const float* gcn_b   = (const float*)d_in[13];
    const float* bn2_g   = (const float*)d_in[14];
    const float* bn2_b   = (const float*)d_in[15];
    const float* bn2_m   = (const float*)d_in[16];
    const float* bn2_v   = (const float*)d_in[17];
    const float* gate_W  = (const float*)d_in[18];
    const float* gate_b  = (const float*)d_in[19];
    const float* Wih     = (const float*)d_in[20];
    const float* Whh     = (const float*)d_in[21];
    const float* bih     = (const float*)d_in[22];
    const float* bhh     = (const float*)d_in[23];
    const float* fcW     = (const float*)d_in[24];
    const float* fcb     = (const float*)d_in[25];
    float* out = (float*)d_out;

    static cudaStream_t s_lstm = nullptr, s_csr = nullptr;
    static cudaEvent_t evA = nullptr, evB = nullptr, evC = nullptr, evD = nullptr;
    if (s_lstm == nullptr) {
        cudaStreamCreateWithFlags(&s_lstm, cudaStreamNonBlocking);
        cudaStreamCreateWithFlags(&s_csr, cudaStreamNonBlocking);
        cudaEventCreateWithFlags(&evA, cudaEventDisableTiming);
        cudaEventCreateWithFlags(&evB, cudaEventDisableTiming);
        cudaEventCreateWithFlags(&evC, cudaEventDisableTiming);
        cudaEventCreateWithFlags(&evD, cudaEventDisableTiming);
        cudaFuncSetAttribute(k_lstm_persist, cudaFuncAttributeMaxDynamicSharedMemorySize, LSTM_SMEM_BYTES);
        cudaFuncSetAttribute(k_lstm_persist, cudaFuncAttributePreferredSharedMemoryCarveout, 100);
    }

    // fork: LSTM branch
    cudaEventRecord(evA, 0);
    cudaStreamWaitEvent(s_lstm, evA, 0);
    k_xpre<<<dim3(Tt, Bb / 32), 512, 0, s_lstm>>>(quant, Wih, bih, bhh);
    k_lstm_persist<<<LCTAS, 512, LSTM_SMEM_BYTES, s_lstm>>>(Whh);
    cudaEventRecord(evB, s_lstm);

    // fork: CSR build (+ scatter, which no longer needs the GEMM) overlaps with gat_gemm
    cudaEventRecord(evC, 0);
    cudaStreamWaitEvent(s_csr, evC, 0);
    k_init<<<(Nn + 511) / 512, 512, 0, s_csr>>>();
    k_count<<<(NeT + 255) / 256, 256, 0, s_csr>>>(ei);
    k_scan1<<<SCAN_B, 512, 0, s_csr>>>();
    k_scan2<<<1, 32, 0, s_csr>>>();
    k_scan3<<<SCAN_B, 512, 0, s_csr>>>();
    k_scatter<<<(NeT + 255) / 256, 256, 0, s_csr>>>(ei);
    cudaEventRecord(evD, s_csr);

    // graph branch on main stream
    k_gat_gemm<<<(Nn + 63) / 64, 256>>>(x, gat_W, att_src, att_dst);
    cudaStreamWaitEvent(0, evD, 0);
    k_gather3<<<(Nn + 7) / 8, 256>>>(gat_b, bn1_g, bn1_b, bn1_m, bn1_v);
    k_gcn_gemm<<<(Nn + 63) / 64, 256>>>(gcn_W);
    k_gather4<<<(Nn + 7) / 8, 256>>>(gcn_b, bn2_g, bn2_b, bn2_m, bn2_v, gate_W, gate_b);
    k_pool<<<Bb, 128>>>(batch);

    // join
    cudaStreamWaitEvent(0, evB, 0);
    k_final<<<1, 256>>>(fcW, fcb, out);
}

// round 8
// speedup vs baseline: 3.0753x; 1.1289x over previous
#include <cuda_runtime.h>
#include <cuda_bf16.h>
#include <cstdint>
#include <math.h>

// ---------------- problem constants ----------------
constexpr int Nn  = 50000;     // nodes
constexpr int Ne  = 800000;    // edges (without self loops)
constexpr int NeT = 850000;    // edges + self loops
constexpr int Bb  = 256;       // graphs / batch
constexpr int Tt  = 50;        // timesteps
constexpr int DIM = 128;       // feature dim
constexpr int LH  = 128;       // lstm hidden
constexpr int QD  = 32;        // lstm input dim
constexpr int CAP = 64;        // per-row smem edge cache
constexpr int SCAN_B = (Nn + 511) / 512;   // 98
constexpr int LCTAS = 128;     // persistent LSTM CTAs
constexpr int BPC = Bb / LCTAS; // 2 batches per CTA

constexpr int SW_FLOATS = 512 * 68;
constexpr int SH_FLOATS = BPC * 128;
constexpr int SG_FLOATS = BPC * 512;
constexpr int LSTM_SMEM_BYTES = (SW_FLOATS + SH_FLOATS + SG_FLOATS) * 4;

// ---------------- device scratch ----------------
__device__ __nv_bfloat16 d_xwh[Nn * DIM];   // bf16 xw rows (gather3 input)
__device__ __nv_bfloat16 d_hwh[Nn * DIM];   // bf16 hw*dinv rows (gather4 input)
__device__ float    d_asrc[Nn * 4];
__device__ float    d_adst[Nn * 4];
__device__ int      d_degi[Nn];
__device__ int      d_cnt[Nn];
__device__ int      d_off[Nn + 1];
__device__ int      d_bsum[SCAN_B];
__device__ int      d_bsx[SCAN_B];
__device__ int      d_srcs[NeT];
__device__ float    d_h[Nn * DIM];
__device__ float    d_dinv[Nn];
__device__ float    d_h2[Nn * DIM];
__device__ float    d_gate[Nn];
__device__ float    d_grep[Bb * DIM];
__device__ float    d_xpre[Bb * Tt * 4 * LH];
__device__ float    d_hT[LH * Bb];

__device__ __forceinline__ float sigf(float x) { return 1.0f / (1.0f + __expf(-x)); }
__device__ __forceinline__ float lrelu(float x) { return x > 0.f ? x : 0.2f * x; }
__device__ __forceinline__ uint32_t f2bf2u(float a, float b) {
    __nv_bfloat162 t = __floats2bfloat162_rn(a, b);
    return *reinterpret_cast<uint32_t*>(&t);
}
__device__ __forceinline__ float2 u2f2(uint32_t u) {
    __nv_bfloat162 t = *reinterpret_cast<__nv_bfloat162*>(&u);
    return __bfloat1622float2(t);
}

// ---------------- init ----------------
__global__ void k_init() {
    int i = blockIdx.x * blockDim.x + threadIdx.x;
    if (i < Nn) { d_degi[i] = 0; d_cnt[i] = 0; }
}

// ---------------- GAT gemm: 8 rows/warp, bf16 output ----------------
__global__ __launch_bounds__(256) void k_gat_gemm(const float* __restrict__ x, const float* __restrict__ W,
                                                  const float* __restrict__ att_s, const float* __restrict__ att_d) {
    __shared__ float sx[64][DIM];
    int tid = threadIdx.x, w = tid >> 5, lane = tid & 31;
    int base = blockIdx.x * 64;
    for (int idx = tid; idx < 64 * 32; idx += 256) {
        int rl = idx >> 5, c4 = idx & 31;
        int gr = base + rl;
        float4 v = (gr < Nn) ? reinterpret_cast<const float4*>(x + (size_t)gr * DIM)[c4]
                             : make_float4(0.f, 0.f, 0.f, 0.f);
        reinterpret_cast<float4*>(sx[rl])[c4] = v;
    }
    __syncthreads();
    const float4* W4 = reinterpret_cast<const float4*>(W);
    float4 acc[8];
#pragma unroll
    for (int r = 0; r < 8; r++) acc[r] = make_float4(0.f, 0.f, 0.f, 0.f);
    int rb = w * 8;
#pragma unroll 4
    for (int k = 0; k < DIM; k++) {
        float4 wv = W4[k * 32 + lane];
#pragma unroll
        for (int r = 0; r < 8; r++) {
            float xk = sx[rb + r][k];
            acc[r].x += xk * wv.x; acc[r].y += xk * wv.y;
            acc[r].z += xk * wv.z; acc[r].w += xk * wv.w;
        }
    }
    int c0 = lane * 4;
    float s0 = att_s[c0], s1 = att_s[c0 + 1], s2 = att_s[c0 + 2], s3 = att_s[c0 + 3];
    float d0 = att_d[c0], d1 = att_d[c0 + 1], d2 = att_d[c0 + 2], d3 = att_d[c0 + 3];
#pragma unroll
    for (int r = 0; r < 8; r++) {
        int gr = base + rb + r;
        if (gr >= Nn) break;
        uint2 pk;
        pk.x = f2bf2u(acc[r].x, acc[r].y);
        pk.y = f2bf2u(acc[r].z, acc[r].w);
        reinterpret_cast<uint2*>(d_xwh + (size_t)gr * DIM)[lane] = pk;   // cols 4l..4l+3
        float ps = acc[r].x * s0 + acc[r].y * s1 + acc[r].z * s2 + acc[r].w * s3;
        float pd = acc[r].x * d0 + acc[r].y * d1 + acc[r].z * d2 + acc[r].w * d3;
#pragma unroll
        for (int off = 4; off; off >>= 1) {
            ps += __shfl_xor_sync(0xffffffffu, ps, off);
            pd += __shfl_xor_sync(0xffffffffu, pd, off);
        }
        if ((lane & 7) == 0) {
            int h = lane >> 3;
            d_asrc[gr * 4 + h] = ps;
            d_adst[gr * 4 + h] = pd;
        }
    }
}

// ---------------- CSR build ----------------
__global__ void k_count(const int* __restrict__ ei) {
    int e = blockIdx.x * blockDim.x + threadIdx.x;
    if (e >= NeT) return;
    int d = (e < Ne) ? ei[Ne + e] : e - Ne;
    atomicAdd(&d_degi[d], 1);
}

__global__ void k_scan1() {
    __shared__ int wsum[16];
    int i = blockIdx.x * 512 + threadIdx.x;
    int v = (i < Nn) ? d_degi[i] : 0;
    int lane = threadIdx.x & 31, wid = threadIdx.x >> 5;
    int inc = v;
#pragma unroll
    for (int o = 1; o < 32; o <<= 1) {
        int t = __shfl_up_sync(0xffffffffu, inc, o);
        if (lane >= o) inc += t;
    }
    if (lane == 31) wsum[wid] = inc;
    __syncthreads();
    if (wid == 0) {
        int wv = (lane < 16) ? wsum[lane] : 0;
#pragma unroll
        for (int o = 1; o < 16; o <<= 1) {
            int t = __shfl_up_sync(0xffffffffu, wv, o);
            if (lane >= o) wv += t;
        }
        if (lane < 16) wsum[lane] = wv;
    }
    __syncthreads();
    int woff = (wid > 0) ? wsum[wid - 1] : 0;
    if (i < Nn) d_off[i] = woff + inc - v;
    if (threadIdx.x == 0) d_bsum[blockIdx.x] = wsum[15];
}

__global__ void k_scan2() {
    if (threadIdx.x != 0 || blockIdx.x != 0) return;
    int run = 0;
    for (int i = 0; i < SCAN_B; i++) { int t = d_bsum[i]; d_bsx[i] = run; run += t; }
}

__global__ void k_scan3() {
    int i = blockIdx.x * 512 + threadIdx.x;
    if (i < Nn) d_off[i] += d_bsx[blockIdx.x];
    if (i == 0) d_off[Nn] = NeT;
}

__global__ void k_scatter(const int* __restrict__ ei) {
    int e = blockIdx.x * blockDim.x + threadIdx.x;
    if (e >= NeT) return;
    int s, d;
    if (e < Ne) { s = ei[e]; d = ei[Ne + e]; } else { s = d = e - Ne; }
    int pos = d_off[d] + atomicAdd(&d_cnt[d], 1);
    d_srcs[pos] = s;
}

// ---------------- gather3: softmax + bf16 aggregate + bias/elu/bn1 ----------------
// lane owns columns {2l, 2l+1, 64+2l, 64+2l+1}
__global__ __launch_bounds__(256) void k_gather3(const float* __restrict__ gat_b,
                                                 const float* __restrict__ g1, const float* __restrict__ b1,
                                                 const float* __restrict__ m1, const float* __restrict__ v1) {
    __shared__ float sex[8][CAP * 4];
    __shared__ int   ssrc[8][CAP];
    int w = threadIdx.x >> 5, lane = threadIdx.x & 31;
    int n = blockIdx.x * 8 + w;
    if (n >= Nn) return;
    int row = d_off[n], end = d_off[n + 1], len = end - row;
    float4 ad = *reinterpret_cast<const float4*>(d_adst + n * 4);

    // A1: gather asrc, leaky scores, cache, max-reduce
    float m0 = -1e30f, m1v = -1e30f, m2v = -1e30f, m3v = -1e30f;
    for (int base = 0; base < len; base += 32) {
        int j = base + lane;
        if (j < len) {
            int s = d_srcs[row + j];
            float4 as = *reinterpret_cast<const float4*>(d_asrc + s * 4);
            float4 v;
            v.x = lrelu(as.x + ad.x); v.y = lrelu(as.y + ad.y);
            v.z = lrelu(as.z + ad.z); v.w = lrelu(as.w + ad.w);
            if (j < CAP) { *reinterpret_cast<float4*>(&sex[w][j * 4]) = v; ssrc[w][j] = s; }
            m0 = fmaxf(m0, v.x); m1v = fmaxf(m1v, v.y); m2v = fmaxf(m2v, v.z); m3v = fmaxf(m3v, v.w);
        }
    }
#pragma unroll
    for (int o = 16; o; o >>= 1) {
        m0  = fmaxf(m0,  __shfl_xor_sync(0xffffffffu, m0,  o));
        m1v = fmaxf(m1v, __shfl_xor_sync(0xffffffffu, m1v, o));
        m2v = fmaxf(m2v, __shfl_xor_sync(0xffffffffu, m2v, o));
        m3v = fmaxf(m3v, __shfl_xor_sync(0xffffffffu, m3v, o));
    }
    // A2: exp + sum
    float s0 = 0.f, s1 = 0.f, s2 = 0.f, s3 = 0.f;
    for (int base = 0; base < len; base += 32) {
        int j = base + lane;
        if (j < len) {
            float4 v;
            if (j < CAP) v = *reinterpret_cast<float4*>(&sex[w][j * 4]);
            else {
                int s = d_srcs[row + j];
                float4 as = *reinterpret_cast<const float4*>(d_asrc + s * 4);
                v.x = lrelu(as.x + ad.x); v.y = lrelu(as.y + ad.y);
                v.z = lrelu(as.z + ad.z); v.w = lrelu(as.w + ad.w);
            }
            v.x = __expf(v.x - m0);  v.y = __expf(v.y - m1v);
            v.z = __expf(v.z - m2v); v.w = __expf(v.w - m3v);
            if (j < CAP) *reinterpret_cast<float4*>(&sex[w][j * 4]) = v;
            s0 += v.x; s1 += v.y; s2 += v.z; s3 += v.w;
        }
    }
#pragma unroll
    for (int o = 16; o; o >>= 1) {
        s0 += __shfl_xor_sync(0xffffffffu, s0, o);
        s1 += __shfl_xor_sync(0xffffffffu, s1, o);
        s2 += __shfl_xor_sync(0xffffffffu, s2, o);
        s3 += __shfl_xor_sync(0xffffffffu, s3, o);
    }
    float r0 = 1.0f / (s0 + 1e-16f), r1 = 1.0f / (s1 + 1e-16f);
    float r2 = 1.0f / (s2 + 1e-16f), r3 = 1.0f / (s3 + 1e-16f);

    __syncwarp();
    // B: bf16 aggregate, x4 unroll
    bool hiSel = (lane >= 16);
    float alo0 = 0.f, alo1 = 0.f, ahi0 = 0.f, ahi1 = 0.f;
    int jmax = len < CAP ? len : CAP;
    int j = 0;
    for (; j + 4 <= jmax; j += 4) {
        uint32_t ulo[4], uhi[4];
#pragma unroll
        for (int e = 0; e < 4; e++) {
            int sI = ssrc[w][j + e];
            const uint32_t* xr = reinterpret_cast<const uint32_t*>(d_xwh + (size_t)sI * DIM);
            ulo[e] = xr[lane];
            uhi[e] = xr[lane + 32];
        }
#pragma unroll
        for (int e = 0; e < 4; e++) {
            float a0 = sex[w][(j + e) * 4 + 0] * r0, a1 = sex[w][(j + e) * 4 + 1] * r1;
            float a2 = sex[w][(j + e) * 4 + 2] * r2, a3 = sex[w][(j + e) * 4 + 3] * r3;
            float wlo = hiSel ? a1 : a0;
            float whi = hiSel ? a3 : a2;
            float2 lo = u2f2(ulo[e]), hi = u2f2(uhi[e]);
            alo0 += lo.x * wlo; alo1 += lo.y * wlo;
            ahi0 += hi.x * whi; ahi1 += hi.y * whi;
        }
    }
    for (; j < jmax; j++) {
        int sI = ssrc[w][j];
        const uint32_t* xr = reinterpret_cast<const uint32_t*>(d_xwh + (size_t)sI * DIM);
        float a0 = sex[w][j * 4 + 0] * r0, a1 = sex[w][j * 4 + 1] * r1;
        float a2 = sex[w][j * 4 + 2] * r2, a3 = sex[w][j * 4 + 3] * r3;
        float wlo = hiSel ? a1 : a0;
        float whi = hiSel ? a3 : a2;
        float2 lo = u2f2(xr[lane]), hi = u2f2(xr[lane + 32]);
        alo0 += lo.x * wlo; alo1 += lo.y * wlo;
        ahi0 += hi.x * whi; ahi1 += hi.y * whi;
    }
    for (; j < len; j++) {  // rare tail beyond CAP
        int sI = d_srcs[row + j];
        float4 as = *reinterpret_cast<const float4*>(d_asrc + sI * 4);
        float a0 = __expf(lrelu(as.x + ad.x) - m0)  * r0;
        float a1 = __expf(lrelu(as.y + ad.y) - m1v) * r1;
        float a2 = __expf(lrelu(as.z + ad.z) - m2v) * r2;
        float a3 = __expf(lrelu(as.w + ad.w) - m3v) * r3;
        float wlo = hiSel ? a1 : a0;
        float whi = hiSel ? a3 : a2;
        const uint32_t* xr = reinterpret_cast<const uint32_t*>(d_xwh + (size_t)sI * DIM);
        float2 lo = u2f2(xr[lane]), hi = u2f2(xr[lane + 32]);
        alo0 += lo.x * wlo; alo1 += lo.y * wlo;
        ahi0 += hi.x * whi; ahi1 += hi.y * whi;
    }
    // epilogue: bias + elu + bn1 on owned columns
    int clo = lane * 2, chi = 64 + lane * 2;
    float vals[4] = {alo0, alo1, ahi0, ahi1};
    int cols[4] = {clo, clo + 1, chi, chi + 1};
#pragma unroll
    for (int q = 0; q < 4; q++) {
        int c = cols[q];
        float v = vals[q] + gat_b[c];
        v = v > 0.f ? v : (__expf(v) - 1.0f);
        vals[q] = g1[c] * (v - m1[c]) * rsqrtf(v1[c] + 1e-5f) + b1[c];
    }
    *reinterpret_cast<float2*>(d_h + (size_t)n * DIM + clo) = make_float2(vals[0], vals[1]);
    *reinterpret_cast<float2*>(d_h + (size_t)n * DIM + chi) = make_float2(vals[2], vals[3]);
    if (lane == 0) d_dinv[n] = rsqrtf((float)len);
}

// ---------------- GCN gemm: 8 rows/warp, bf16 output pre-scaled by dinv[row] ----------------
__global__ __launch_bounds__(256) void k_gcn_gemm(const float* __restrict__ W) {
    __shared__ float sx[64][DIM];
    int tid = threadIdx.x, w = tid >> 5, lane = tid & 31;
    int base = blockIdx.x * 64;
    for (int idx = tid; idx < 64 * 32; idx += 256) {
        int rl = idx >> 5, c4 = idx & 31;
        int gr = base + rl;
        float4 v = (gr < Nn) ? reinterpret_cast<const float4*>(d_h + (size_t)gr * DIM)[c4]
                             : make_float4(0.f, 0.f, 0.f, 0.f);
        reinterpret_cast<float4*>(sx[rl])[c4] = v;
    }
    __syncthreads();
    const float4* W4 = reinterpret_cast<const float4*>(W);
    float4 acc[8];
#pragma unroll
    for (int r = 0; r < 8; r++) acc[r] = make_float4(0.f, 0.f, 0.f, 0.f);
    int rb = w * 8;
#pragma unroll 4
    for (int k = 0; k < DIM; k++) {
        float4 wv = W4[k * 32 + lane];
#pragma unroll
        for (int r = 0; r < 8; r++) {
            float xk = sx[rb + r][k];
            acc[r].x += xk * wv.x; acc[r].y += xk * wv.y;
            acc[r].z += xk * wv.z; acc[r].w += xk * wv.w;
        }
    }
#pragma unroll
    for (int r = 0; r < 8; r++) {
        int gr = base + rb + r;
        if (gr < Nn) {
            float dv = d_dinv[gr];
            uint2 pk;
            pk.x = f2bf2u(acc[r].x * dv, acc[r].y * dv);
            pk.y = f2bf2u(acc[r].z * dv, acc[r].w * dv);
            reinterpret_cast<uint2*>(d_hwh + (size_t)gr * DIM)[lane] = pk;
        }
    }
}

// ---------------- gather4: unweighted bf16 sum ×dinv[n] + bias/elu/bn2 + gate ----------------
__global__ __launch_bounds__(256) void k_gather4(const float* __restrict__ gcn_b,
                                                 const float* __restrict__ g2, const float* __restrict__ b2,
                                                 const float* __restrict__ m2, const float* __restrict__ v2,
                                                 const float* __restrict__ gateW, const float* __restrict__ gate_b) {
    int lane = threadIdx.x & 31;
    int n = blockIdx.x * 8 + (threadIdx.x >> 5);
    if (n >= Nn) return;
    int row = d_off[n], end = d_off[n + 1];
    float dn = d_dinv[n];
    float alo0 = 0.f, alo1 = 0.f, ahi0 = 0.f, ahi1 = 0.f;
    int j = row;
    for (; j + 4 <= end; j += 4) {
        uint32_t ulo[4], uhi[4];
#pragma unroll
        for (int e = 0; e < 4; e++) {
            int sI = d_srcs[j + e];
            const uint32_t* xr = reinterpret_cast<const uint32_t*>(d_hwh + (size_t)sI * DIM);
            ulo[e] = xr[lane];
            uhi[e] = xr[lane + 32];
        }
#pragma unroll
        for (int e = 0; e < 4; e++) {
            float2 lo = u2f2(ulo[e]), hi = u2f2(uhi[e]);
            alo0 += lo.x; alo1 += lo.y;
            ahi0 += hi.x; ahi1 += hi.y;
        }
    }
    for (; j < end; j++) {
        int sI = d_srcs[j];
        const uint32_t* xr = reinterpret_cast<const uint32_t*>(d_hwh + (size_t)sI * DIM);
        float2 lo = u2f2(xr[lane]), hi = u2f2(xr[lane + 32]);
        alo0 += lo.x; alo1 += lo.y;
        ahi0 += hi.x; ahi1 += hi.y;
    }
    int clo = lane * 2, chi = 64 + lane * 2;
    float vals[4] = {alo0 * dn, alo1 * dn, ahi0 * dn, ahi1 * dn};
    int cols[4] = {clo, clo + 1, chi, chi + 1};
    float p = 0.f;
#pragma unroll
    for (int q = 0; q < 4; q++) {
        int c = cols[q];
        float v = vals[q] + gcn_b[c];
        v = v > 0.f ? v : (__expf(v) - 1.0f);
        v = g2[c] * (v - m2[c]) * rsqrtf(v2[c] + 1e-5f) + b2[c];
        vals[q] = v;
        p += v * gateW[c];
    }
    *reinterpret_cast<float2*>(d_h2 + (size_t)n * DIM + clo) = make_float2(vals[0], vals[1]);
    *reinterpret_cast<float2*>(d_h2 + (size_t)n * DIM + chi) = make_float2(vals[2], vals[3]);
#pragma unroll
    for (int o = 16; o; o >>= 1) p += __shfl_xor_sync(0xffffffffu, p, o);
    if (lane == 0) d_gate[n] = p + gate_b[0];
}

// ---------------- pooling ----------------
__global__ __launch_bounds__(128) void k_pool(const int* __restrict__ batch) {
    __shared__ int sr[2];
    __shared__ float smax[4], ssum[4];
    int b = blockIdx.x;
    int tid = threadIdx.x, lane = tid & 31, wid = tid >> 5;
    if (tid == 0) {
        int lo = 0, hi = Nn;
        while (lo < hi) { int m = (lo + hi) >> 1; if (batch[m] < b) lo = m + 1; else hi = m; }
        sr[0] = lo;
        int lo2 = lo, hi2 = Nn;
        while (lo2 < hi2) { int m = (lo2 + hi2) >> 1; if (batch[m] < b + 1) lo2 = m + 1; else hi2 = m; }
        sr[1] = lo2;
    }
    __syncthreads();
    int lo = sr[0], hi = sr[1];
    if (lo >= hi) { d_grep[(size_t)b * DIM + tid] = 0.f; return; }
    float mv = -1e30f;
    for (int n = lo + tid; n < hi; n += 128) mv = fmaxf(mv, d_gate[n]);
#pragma unroll
    for (int o = 16; o; o >>= 1) mv = fmaxf(mv, __shfl_xor_sync(0xffffffffu, mv, o));
    if (lane == 0) smax[wid] = mv;
    __syncthreads();
    mv = fmaxf(fmaxf(smax[0], smax[1]), fmaxf(smax[2], smax[3]));
    float sv = 0.f;
    for (int n = lo + tid; n < hi; n += 128) sv += __expf(d_gate[n] - mv);
#pragma unroll
    for (int o = 16; o; o >>= 1) sv += __shfl_xor_sync(0xffffffffu, sv, o);
    if (lane == 0) ssum[wid] = sv;
    __syncthreads();
    sv = ssum[0] + ssum[1] + ssum[2] + ssum[3];
    float rcp = 1.0f / (sv + 1e-16f);
    float acc = 0.f;
    int n = lo;
    for (; n + 2 <= hi; n += 2) {
        float wA = __expf(d_gate[n] - mv) * rcp;
        float wB = __expf(d_gate[n + 1] - mv) * rcp;
        acc += wA * d_h2[(size_t)n * DIM + tid] + wB * d_h2[(size_t)(n + 1) * DIM + tid];
    }
    if (n < hi) acc += __expf(d_gate[n] - mv) * rcp * d_h2[(size_t)n * DIM + tid];
    d_grep[(size_t)b * DIM + tid] = acc;
}

// ---------------- LSTM input projection ----------------
__global__ void k_xpre(const float* __restrict__ quant, const float* __restrict__ Wih,
                       const float* __restrict__ bih, const float* __restrict__ bhh) {
    __shared__ float4 sq[32][8];
    int t = blockIdx.x;
    int bbase = blockIdx.y * 32;
    int tid = threadIdx.x;  // 512
    for (int i = tid; i < 32 * 8; i += 512) {
        int b = i >> 3, k = i & 7;
        sq[b][k] = reinterpret_cast<const float4*>(quant + ((size_t)(bbase + b) * Tt + t) * QD)[k];
    }
    __syncthreads();
    int j = tid;
    float wr[QD];
#pragma unroll
    for (int k = 0; k < QD; k++) wr[k] = Wih[j * QD + k];
    float bs = bih[j] + bhh[j];
    for (int b = 0; b < 32; b++) {
        float acc = bs;
#pragma unroll
        for (int k8 = 0; k8 < 8; k8++) {
            float4 q = sq[b][k8];
            acc += q.x * wr[k8 * 4] + q.y * wr[k8 * 4 + 1] + q.z * wr[k8 * 4 + 2] + q.w * wr[k8 * 4 + 3];
        }
        d_xpre[((size_t)(bbase + b) * Tt + t) * 512 + j] = acc;
    }
}

// ---------------- persistent LSTM ----------------
__global__ __launch_bounds__(512) void k_lstm_persist(const float* __restrict__ Whh) {
    extern __shared__ float dyn[];
    float* s_w    = dyn;
    float* s_h    = dyn + SW_FLOATS;
    float* s_gate = dyn + SW_FLOATS + SH_FLOATS;
    int j = threadIdx.x;

    float4 w4[16];
    const float4* Wr = reinterpret_cast<const float4*>(Whh + (size_t)j * 128);
#pragma unroll
    for (int q = 0; q < 16; q++) w4[q] = Wr[q];
#pragma unroll
    for (int q = 0; q < 16; q++) {
        float4 v = Wr[16 + q];
        *reinterpret_cast<float4*>(&s_w[j * 68 + q * 4]) = v;
    }
    if (j < BPC * 128) s_h[j] = 0.f;
    float c0 = 0.f, c1 = 0.f;
    __syncthreads();

    int bglob = blockIdx.x * BPC;
    const float* xp0 = d_xpre + (size_t)(bglob + 0) * Tt * 512;
    const float* xp1 = d_xpre + (size_t)(bglob + 1) * Tt * 512;

    for (int t = 0; t < Tt; t++) {
        float x0 = xp0[t * 512 + j];
        float x1 = xp1[t * 512 + j];
        float a0 = 0.f, a1 = 0.f;
#pragma unroll
        for (int q = 0; q < 16; q++) {
            float4 h0 = *reinterpret_cast<const float4*>(&s_h[0 * 128 + q * 4]);
            float4 h1 = *reinterpret_cast<const float4*>(&s_h[1 * 128 + q * 4]);
            float4 wv = w4[q];
            a0 += wv.x * h0.x + wv.y * h0.y + wv.z * h0.z + wv.w * h0.w;
            a1 += wv.x * h1.x + wv.y * h1.y + wv.z * h1.z + wv.w * h1.w;
        }
#pragma unroll
        for (int q = 0; q < 16; q++) {
            float4 wv = *reinterpret_cast<const float4*>(&s_w[j * 68 + q * 4]);
            float4 h0 = *reinterpret_cast<const float4*>(&s_h[0 * 128 + 64 + q * 4]);
            float4 h1 = *reinterpret_cast<const float4*>(&s_h[1 * 128 + 64 + q * 4]);
            a0 += wv.x * h0.x + wv.y * h0.y + wv.z * h0.z + wv.w * h0.w;
            a1 += wv.x * h1.x + wv.y * h1.y + wv.z * h1.z + wv.w * h1.w;
        }
        s_gate[0 * 512 + j] = a0 + x0;
        s_gate[1 * 512 + j] = a1 + x1;
        __syncthreads();
        if (j < 256) {
            int b = j >> 7, u = j & 127;
            float gi = s_gate[b * 512 + u];
            float gf = s_gate[b * 512 + 128 + u];
            float gg = s_gate[b * 512 + 256 + u];
            float go = s_gate[b * 512 + 384 + u];
            float cv = (j < 128) ? c0 : c1;
            cv = sigf(gf) * cv + sigf(gi) * tanhf(gg);
            if (j < 128) c0 = cv; else c1 = cv;
            s_h[b * 128 + u] = sigf(go) * tanhf(cv);
        }
        __syncthreads();
    }
    if (j < BPC * 128) {
        int b = j >> 7, u = j & 127;
        d_hT[u * Bb + (bglob + b)] = s_h[b * 128 + u];
    }
}

// ---------------- final linear ----------------
__global__ void k_final(const float* __restrict__ fcW, const float* __restrict__ fcb,
                        float* __restrict__ out) {
    int b = threadIdx.x;  // 256
    float acc = fcb[0];
#pragma unroll 4
    for (int c = 0; c < DIM; c++) acc += d_grep[b * DIM + c] * fcW[c];
#pragma unroll 4
    for (int u = 0; u < LH; u++) acc += d_hT[u * Bb + b] * fcW[DIM + u];
    out[b] = acc;
}

// ---------------- launch ----------------
extern "C" void kernel_launch(void* const* d_in, const int* in_sizes, int n_in,
                              void* d_out, int out_size) {
    (void)in_sizes; (void)n_in; (void)out_size;
    const float* x       = (const float*)d_in[0];
    const int*   ei      = (const int*)d_in[1];
    const int*   batch   = (const int*)d_in[2];
    const float* quant   = (const float*)d_in[3];
    const float* gat_W   = (const float*)d_in[4];
    const float* att_src = (const float*)d_in[5];
    const float* att_dst = (const float*)d_in[6];
    const float* gat_b   = (const float*)d_in[7];
    const float* bn1_g   = (const float*)d_in[8];
    const float* bn1_b   = (const float*)d_in[9];
    const float* bn1_m   = (const float*)d_in[10];
    const float* bn1_v   = (const float*)d_in[11];
    const float* gcn_W   = (const float*)d_in[12];
    const float* gcn_b   = (const float*)d_in[13];
    const float* bn2_g   = (const float*)d_in[14];
    const float* bn2_b   = (const float*)d_in[15];
    const float* bn2_m   = (const float*)d_in[16];
    const float* bn2_v   = (const float*)d_in[17];
    const float* gate_W  = (const float*)d_in[18];
    const float* gate_b  = (const float*)d_in[19];
    const float* Wih     = (const float*)d_in[20];
    const float* Whh     = (const float*)d_in[21];
    const float* bih     = (const float*)d_in[22];
    const float* bhh     = (const float*)d_in[23];
    const float* fcW     = (const float*)d_in[24];
    const float* fcb     = (const float*)d_in[25];
    float* out = (float*)d_out;

    static cudaStream_t s_lstm = nullptr, s_csr = nullptr;
    static cudaEvent_t evA = nullptr, evB = nullptr, evC = nullptr, evD = nullptr;
    if (s_lstm == nullptr) {
        cudaStreamCreateWithFlags(&s_lstm, cudaStreamNonBlocking);
        cudaStreamCreateWithFlags(&s_csr, cudaStreamNonBlocking);
        cudaEventCreateWithFlags(&evA, cudaEventDisableTiming);
        cudaEventCreateWithFlags(&evB, cudaEventDisableTiming);
        cudaEventCreateWithFlags(&evC, cudaEventDisableTiming);
        cudaEventCreateWithFlags(&evD, cudaEventDisableTiming);
        cudaFuncSetAttribute(k_lstm_persist, cudaFuncAttributeMaxDynamicSharedMemorySize, LSTM_SMEM_BYTES);
        cudaFuncSetAttribute(k_lstm_persist, cudaFuncAttributePreferredSharedMemoryCarveout, 100);
    }

    // fork: LSTM branch
    cudaEventRecord(evA, 0);
    cudaStreamWaitEvent(s_lstm, evA, 0);
    k_xpre<<<dim3(Tt, Bb / 32), 512, 0, s_lstm>>>(quant, Wih, bih, bhh);
    k_lstm_persist<<<LCTAS, 512, LSTM_SMEM_BYTES, s_lstm>>>(Whh);
    cudaEventRecord(evB, s_lstm);

    // fork: CSR build + scatter overlap with gat_gemm
    cudaEventRecord(evC, 0);
    cudaStreamWaitEvent(s_csr, evC, 0);
    k_init<<<(Nn + 511) / 512, 512, 0, s_csr>>>();
    k_count<<<(NeT + 255) / 256, 256, 0, s_csr>>>(ei);
    k_scan1<<<SCAN_B, 512, 0, s_csr>>>();
    k_scan2<<<1, 32, 0, s_csr>>>();
    k_scan3<<<SCAN_B, 512, 0, s_csr>>>();
    k_scatter<<<(NeT + 255) / 256, 256, 0, s_csr>>>(ei);
    cudaEventRecord(evD, s_csr);

    // graph branch
    k_gat_gemm<<<(Nn + 63) / 64, 256>>>(x, gat_W, att_src, att_dst);
    cudaStreamWaitEvent(0, evD, 0);
    k_gather3<<<(Nn + 7) / 8, 256>>>(gat_b, bn1_g, bn1_b, bn1_m, bn1_v);
    k_gcn_gemm<<<(Nn + 63) / 64, 256>>>(gcn_W);
    k_gather4<<<(Nn + 7) / 8, 256>>>(gcn_b, bn2_g, bn2_b, bn2_m, bn2_v, gate_W, gate_b);
    k_pool<<<Bb, 128>>>(batch);

    // join
    cudaStreamWaitEvent(0, evB, 0);
    k_final<<<1, 256>>>(fcW, fcb, out);
}

// round 15
// speedup vs baseline: 3.0979x; 1.0074x over previous
#include <cuda_runtime.h>
#include <cuda_bf16.h>
#include <cstdint>
#include <math.h>

// ---------------- problem constants ----------------
constexpr int Nn  = 50000;     // nodes
constexpr int Ne  = 800000;    // edges (without self loops)
constexpr int NeT = 850000;    // edges + self loops
constexpr int Bb  = 256;       // graphs / batch
constexpr int Tt  = 50;        // timesteps
constexpr int DIM = 128;       // feature dim
constexpr int LH  = 128;       // lstm hidden
constexpr int QD  = 32;        // lstm input dim
constexpr int CAP = 64;        // per-row smem edge cache
constexpr int SCAN_B = (Nn + 511) / 512;   // 98
constexpr int LCTAS = 128;     // persistent LSTM CTAs
constexpr int BPC = Bb / LCTAS; // 2 batches per CTA
constexpr int SPL = 25024;     // pipeline split (multiple of 64 and 8)

constexpr int SW_FLOATS = 512 * 68;
constexpr int SH_FLOATS = BPC * 128;
constexpr int SG_FLOATS = BPC * 512;
constexpr int LSTM_SMEM_BYTES = (SW_FLOATS + SH_FLOATS + SG_FLOATS) * 4;

// ---------------- device scratch ----------------
__device__ __nv_bfloat16 d_xwh[Nn * DIM];   // bf16 xw rows (gather3 input)
__device__ __nv_bfloat16 d_hb[Nn * DIM];    // bf16 post-bn1 h rows (gcn input)
__device__ __nv_bfloat16 d_hwh[Nn * DIM];   // bf16 hw*dinv rows (gather4 input)
__device__ float    d_asrc[Nn * 4];
__device__ float    d_adst[Nn * 4];
__device__ int      d_degi[Nn];
__device__ int      d_cnt[Nn];
__device__ int      d_off[Nn + 1];
__device__ int      d_bsum[SCAN_B];
__device__ int      d_bsx[SCAN_B];
__device__ int      d_srcs[NeT];
__device__ float    d_dinv[Nn];
__device__ float    d_h2[Nn * DIM];
__device__ float    d_gate[Nn];
__device__ float    d_grep[Bb * DIM];
__device__ float    d_xpre[Bb * Tt * 4 * LH];
__device__ float    d_hT[LH * Bb];

__device__ __forceinline__ float sigf(float x) { return 1.0f / (1.0f + __expf(-x)); }
__device__ __forceinline__ float lrelu(float x) { return x > 0.f ? x : 0.2f * x; }
__device__ __forceinline__ uint32_t f2bf2u(float a, float b) {
    __nv_bfloat162 t = __floats2bfloat162_rn(a, b);
    return *reinterpret_cast<uint32_t*>(&t);
}
__device__ __forceinline__ float2 u2f2(uint32_t u) {
    __nv_bfloat162 t = *reinterpret_cast<__nv_bfloat162*>(&u);
    return __bfloat1622float2(t);
}

// ---------------- init ----------------
__global__ void k_init() {
    int i = blockIdx.x * blockDim.x + threadIdx.x;
    if (i < Nn) { d_degi[i] = 0; d_cnt[i] = 0; }
}

// ---------------- GAT gemm: 8 rows/warp, bf16 output (R8-proven) ----------------
__global__ __launch_bounds__(256) void k_gat_gemm(const float* __restrict__ x, const float* __restrict__ W,
                                                  const float* __restrict__ att_s, const float* __restrict__ att_d) {
    __shared__ float sx[64][DIM];
    int tid = threadIdx.x, w = tid >> 5, lane = tid & 31;
    int base = blockIdx.x * 64;
    for (int idx = tid; idx < 64 * 32; idx += 256) {
        int rl = idx >> 5, c4 = idx & 31;
        int gr = base + rl;
        float4 v = (gr < Nn) ? reinterpret_cast<const float4*>(x + (size_t)gr * DIM)[c4]
                             : make_float4(0.f, 0.f, 0.f, 0.f);
        reinterpret_cast<float4*>(sx[rl])[c4] = v;
    }
    __syncthreads();
    const float4* W4 = reinterpret_cast<const float4*>(W);
    float4 acc[8];
#pragma unroll
    for (int r = 0; r < 8; r++) acc[r] = make_float4(0.f, 0.f, 0.f, 0.f);
    int rb = w * 8;
#pragma unroll 4
    for (int k = 0; k < DIM; k++) {
        float4 wv = W4[k * 32 + lane];
#pragma unroll
        for (int r = 0; r < 8; r++) {
            float xk = sx[rb + r][k];
            acc[r].x += xk * wv.x; acc[r].y += xk * wv.y;
            acc[r].z += xk * wv.z; acc[r].w += xk * wv.w;
        }
    }
    int c0 = lane * 4;
    float s0 = att_s[c0], s1 = att_s[c0 + 1], s2 = att_s[c0 + 2], s3 = att_s[c0 + 3];
    float d0 = att_d[c0], d1 = att_d[c0 + 1], d2 = att_d[c0 + 2], d3 = att_d[c0 + 3];
#pragma unroll
    for (int r = 0; r < 8; r++) {
        int gr = base + rb + r;
        if (gr >= Nn) break;
        uint2 pk;
        pk.x = f2bf2u(acc[r].x, acc[r].y);
        pk.y = f2bf2u(acc[r].z, acc[r].w);
        reinterpret_cast<uint2*>(d_xwh + (size_t)gr * DIM)[lane] = pk;
        float ps = acc[r].x * s0 + acc[r].y * s1 + acc[r].z * s2 + acc[r].w * s3;
        float pd = acc[r].x * d0 + acc[r].y * d1 + acc[r].z * d2 + acc[r].w * d3;
#pragma unroll
        for (int off = 4; off; off >>= 1) {
            ps += __shfl_xor_sync(0xffffffffu, ps, off);
            pd += __shfl_xor_sync(0xffffffffu, pd, off);
        }
        if ((lane & 7) == 0) {
            int h = lane >> 3;
            d_asrc[gr * 4 + h] = ps;
            d_adst[gr * 4 + h] = pd;
        }
    }
}

// ---------------- CSR build ----------------
__global__ void k_count(const int* __restrict__ ei) {
    int e = blockIdx.x * blockDim.x + threadIdx.x;
    if (e >= NeT) return;
    int d = (e < Ne) ? ei[Ne + e] : e - Ne;
    atomicAdd(&d_degi[d], 1);
}

__global__ void k_scan1() {
    __shared__ int wsum[16];
    int i = blockIdx.x * 512 + threadIdx.x;
    int v = (i < Nn) ? d_degi[i] : 0;
    int lane = threadIdx.x & 31, wid = threadIdx.x >> 5;
    int inc = v;
#pragma unroll
    for (int o = 1; o < 32; o <<= 1) {
        int t = __shfl_up_sync(0xffffffffu, inc, o);
        if (lane >= o) inc += t;
    }
    if (lane == 31) wsum[wid] = inc;
    __syncthreads();
    if (wid == 0) {
        int wv = (lane < 16) ? wsum[lane] : 0;
#pragma unroll
        for (int o = 1; o < 16; o <<= 1) {
            int t = __shfl_up_sync(0xffffffffu, wv, o);
            if (lane >= o) wv += t;
        }
        if (lane < 16) wsum[lane] = wv;
    }
    __syncthreads();
    int woff = (wid > 0) ? wsum[wid - 1] : 0;
    if (i < Nn) d_off[i] = woff + inc - v;
    if (threadIdx.x == 0) d_bsum[blockIdx.x] = wsum[15];
}

__global__ void k_scan2() {
    if (threadIdx.x != 0 || blockIdx.x != 0) return;
    int run = 0;
    for (int i = 0; i < SCAN_B; i++) { int t = d_bsum[i]; d_bsx[i] = run; run += t; }
}

__global__ void k_scan3() {
    int i = blockIdx.x * 512 + threadIdx.x;
    if (i < Nn) d_off[i] += d_bsx[blockIdx.x];
    if (i == 0) d_off[Nn] = NeT;
}

__global__ void k_scatter(const int* __restrict__ ei) {
    int e = blockIdx.x * blockDim.x + threadIdx.x;
    if (e >= NeT) return;
    int s, d;
    if (e < Ne) { s = ei[e]; d = ei[Ne + e]; } else { s = d = e - Ne; }
    int pos = d_off[d] + atomicAdd(&d_cnt[d], 1);
    d_srcs[pos] = s;
}

// ---------------- gather3 (node range [off, off+cnt)): softmax + bf16 aggregate + bias/elu/bn1 ----------------
__global__ __launch_bounds__(256) void k_gather3(int off, int cnt,
                                                 const float* __restrict__ gat_b,
                                                 const float* __restrict__ g1, const float* __restrict__ b1,
                                                 const float* __restrict__ m1, const float* __restrict__ v1) {
    __shared__ float sex[8][CAP * 4];
    __shared__ int   ssrc[8][CAP];
    int w = threadIdx.x >> 5, lane = threadIdx.x & 31;
    int n = off + blockIdx.x * 8 + w;
    if (n >= off + cnt || n >= Nn) return;
    int row = d_off[n], end = d_off[n + 1], len = end - row;
    float4 ad = *reinterpret_cast<const float4*>(d_adst + n * 4);

    float m0 = -1e30f, m1v = -1e30f, m2v = -1e30f, m3v = -1e30f;
    for (int base = 0; base < len; base += 32) {
        int j = base + lane;
        if (j < len) {
            int s = d_srcs[row + j];
            float4 as = *reinterpret_cast<const float4*>(d_asrc + s * 4);
            float4 v;
            v.x = lrelu(as.x + ad.x); v.y = lrelu(as.y + ad.y);
            v.z = lrelu(as.z + ad.z); v.w = lrelu(as.w + ad.w);
            if (j < CAP) { *reinterpret_cast<float4*>(&sex[w][j * 4]) = v; ssrc[w][j] = s; }
            m0 = fmaxf(m0, v.x); m1v = fmaxf(m1v, v.y); m2v = fmaxf(m2v, v.z); m3v = fmaxf(m3v, v.w);
        }
    }
#pragma unroll
    for (int o = 16; o; o >>= 1) {
        m0  = fmaxf(m0,  __shfl_xor_sync(0xffffffffu, m0,  o));
        m1v = fmaxf(m1v, __shfl_xor_sync(0xffffffffu, m1v, o));
        m2v = fmaxf(m2v, __shfl_xor_sync(0xffffffffu, m2v, o));
        m3v = fmaxf(m3v, __shfl_xor_sync(0xffffffffu, m3v, o));
    }
    float s0 = 0.f, s1 = 0.f, s2 = 0.f, s3 = 0.f;
    for (int base = 0; base < len; base += 32) {
        int j = base + lane;
        if (j < len) {
            float4 v;
            if (j < CAP) v = *reinterpret_cast<float4*>(&sex[w][j * 4]);
            else {
                int s = d_srcs[row + j];
                float4 as = *reinterpret_cast<const float4*>(d_asrc + s * 4);
                v.x = lrelu(as.x + ad.x); v.y = lrelu(as.y + ad.y);
                v.z = lrelu(as.z + ad.z); v.w = lrelu(as.w + ad.w);
            }
            v.x = __expf(v.x - m0);  v.y = __expf(v.y - m1v);
            v.z = __expf(v.z - m2v); v.w = __expf(v.w - m3v);
            if (j < CAP) *reinterpret_cast<float4*>(&sex[w][j * 4]) = v;
            s0 += v.x; s1 += v.y; s2 += v.z; s3 += v.w;
        }
    }
#pragma unroll
    for (int o = 16; o; o >>= 1) {
        s0 += __shfl_xor_sync(0xffffffffu, s0, o);
        s1 += __shfl_xor_sync(0xffffffffu, s1, o);
        s2 += __shfl_xor_sync(0xffffffffu, s2, o);
        s3 += __shfl_xor_sync(0xffffffffu, s3, o);
    }
    float r0 = 1.0f / (s0 + 1e-16f), r1 = 1.0f / (s1 + 1e-16f);
    float r2 = 1.0f / (s2 + 1e-16f), r3 = 1.0f / (s3 + 1e-16f);

    __syncwarp();
    bool hiSel = (lane >= 16);
    float alo0 = 0.f, alo1 = 0.f, ahi0 = 0.f, ahi1 = 0.f;
    int jmax = len < CAP ? len : CAP;
    int j = 0;
    for (; j + 4 <= jmax; j += 4) {
        uint32_t ulo[4], uhi[4];
#pragma unroll
        for (int e = 0; e < 4; e++) {
            int sI = ssrc[w][j + e];
            const uint32_t* xr = reinterpret_cast<const uint32_t*>(d_xwh + (size_t)sI * DIM);
            ulo[e] = xr[lane];
            uhi[e] = xr[lane + 32];
        }
#pragma unroll
        for (int e = 0; e < 4; e++) {
            float a0 = sex[w][(j + e) * 4 + 0] * r0, a1 = sex[w][(j + e) * 4 + 1] * r1;
            float a2 = sex[w][(j + e) * 4 + 2] * r2, a3 = sex[w][(j + e) * 4 + 3] * r3;
            float wlo = hiSel ? a1 : a0;
            float whi = hiSel ? a3 : a2;
            float2 lo = u2f2(ulo[e]), hi = u2f2(uhi[e]);
            alo0 += lo.x * wlo; alo1 += lo.y * wlo;
            ahi0 += hi.x * whi; ahi1 += hi.y * whi;
        }
    }
    for (; j < jmax; j++) {
        int sI = ssrc[w][j];
        const uint32_t* xr = reinterpret_cast<const uint32_t*>(d_xwh + (size_t)sI * DIM);
        float a0 = sex[w][j * 4 + 0] * r0, a1 = sex[w][j * 4 + 1] * r1;
        float a2 = sex[w][j * 4 + 2] * r2, a3 = sex[w][j * 4 + 3] * r3;
        float wlo = hiSel ? a1 : a0;
        float whi = hiSel ? a3 : a2;
        float2 lo = u2f2(xr[lane]), hi = u2f2(xr[lane + 32]);
        alo0 += lo.x * wlo; alo1 += lo.y * wlo;
        ahi0 += hi.x * whi; ahi1 += hi.y * whi;
    }
    for (; j < len; j++) {
        int sI = d_srcs[row + j];
        float4 as = *reinterpret_cast<const float4*>(d_asrc + sI * 4);
        float a0 = __expf(lrelu(as.x + ad.x) - m0)  * r0;
        float a1 = __expf(lrelu(as.y + ad.y) - m1v) * r1;
        float a2 = __expf(lrelu(as.z + ad.z) - m2v) * r2;
        float a3 = __expf(lrelu(as.w + ad.w) - m3v) * r3;
        float wlo = hiSel ? a1 : a0;
        float whi = hiSel ? a3 : a2;
        const uint32_t* xr = reinterpret_cast<const uint32_t*>(d_xwh + (size_t)sI * DIM);
        float2 lo = u2f2(xr[lane]), hi = u2f2(xr[lane + 32]);
        alo0 += lo.x * wlo; alo1 += lo.y * wlo;
        ahi0 += hi.x * whi; ahi1 += hi.y * whi;
    }
    int clo = lane * 2, chi = 64 + lane * 2;
    float vals[4] = {alo0, alo1, ahi0, ahi1};
    int cols[4] = {clo, clo + 1, chi, chi + 1};
#pragma unroll
    for (int q = 0; q < 4; q++) {
        int c = cols[q];
        float v = vals[q] + gat_b[c];
        v = v > 0.f ? v : (__expf(v) - 1.0f);
        vals[q] = g1[c] * (v - m1[c]) * rsqrtf(v1[c] + 1e-5f) + b1[c];
    }
    *reinterpret_cast<uint32_t*>(d_hb + (size_t)n * DIM + clo) = f2bf2u(vals[0], vals[1]);
    *reinterpret_cast<uint32_t*>(d_hb + (size_t)n * DIM + chi) = f2bf2u(vals[2], vals[3]);
    if (lane == 0) d_dinv[n] = rsqrtf((float)len);
}

// ---------------- GCN gemm (row range [rowOff, rowOff+rowCnt)): bf16 in, bf16*dinv out ----------------
__global__ __launch_bounds__(256) void k_gcn_gemm(int rowOff, int rowCnt, const float* __restrict__ W) {
    __shared__ float sx[64][DIM];
    int tid = threadIdx.x, w = tid >> 5, lane = tid & 31;
    int base = rowOff + blockIdx.x * 64;
    for (int idx = tid; idx < 64 * 32; idx += 256) {
        int rl = idx >> 5, c4 = idx & 31;
        int gr = base + rl;
        float4 v;
        if (gr < rowOff + rowCnt && gr < Nn) {
            uint2 u = reinterpret_cast<const uint2*>(d_hb + (size_t)gr * DIM)[c4];
            float2 p0 = u2f2(u.x), p1 = u2f2(u.y);
            v = make_float4(p0.x, p0.y, p1.x, p1.y);
        } else {
            v = make_float4(0.f, 0.f, 0.f, 0.f);
        }
        reinterpret_cast<float4*>(sx[rl])[c4] = v;
    }
    __syncthreads();
    const float4* W4 = reinterpret_cast<const float4*>(W);
    float4 acc[8];
#pragma unroll
    for (int r = 0; r < 8; r++) acc[r] = make_float4(0.f, 0.f, 0.f, 0.f);
    int rb = w * 8;
#pragma unroll 4
    for (int k = 0; k < DIM; k++) {
        float4 wv = W4[k * 32 + lane];
#pragma unroll
        for (int r = 0; r < 8; r++) {
            float xk = sx[rb + r][k];
            acc[r].x += xk * wv.x; acc[r].y += xk * wv.y;
            acc[r].z += xk * wv.z; acc[r].w += xk * wv.w;
        }
    }
#pragma unroll
    for (int r = 0; r < 8; r++) {
        int gr = base + rb + r;
        if (gr < rowOff + rowCnt && gr < Nn) {
            float dv = d_dinv[gr];
            uint2 pk;
            pk.x = f2bf2u(acc[r].x * dv, acc[r].y * dv);
            pk.y = f2bf2u(acc[r].z * dv, acc[r].w * dv);
            reinterpret_cast<uint2*>(d_hwh + (size_t)gr * DIM)[lane] = pk;
        }
    }
}

// ---------------- gather4: unweighted bf16 sum ×dinv[n] + bias/elu/bn2 + gate ----------------
__global__ __launch_bounds__(256) void k_gather4(const float* __restrict__ gcn_b,
                                                 const float* __restrict__ g2, const float* __restrict__ b2,
                                                 const float* __restrict__ m2, const float* __restrict__ v2,
                                                 const float* __restrict__ gateW, const float* __restrict__ gate_b) {
    int lane = threadIdx.x & 31;
    int n = blockIdx.x * 8 + (threadIdx.x >> 5);
    if (n >= Nn) return;
    int row = d_off[n], end = d_off[n + 1];
    float dn = d_dinv[n];
    float alo0 = 0.f, alo1 = 0.f, ahi0 = 0.f, ahi1 = 0.f;
    int j = row;
    for (; j + 4 <= end; j += 4) {
        uint32_t ulo[4], uhi[4];
#pragma unroll
        for (int e = 0; e < 4; e++) {
            int sI = d_srcs[j + e];
            const uint32_t* xr = reinterpret_cast<const uint32_t*>(d_hwh + (size_t)sI * DIM);
            ulo[e] = xr[lane];
            uhi[e] = xr[lane + 32];
        }
#pragma unroll
        for (int e = 0; e < 4; e++) {
            float2 lo = u2f2(ulo[e]), hi = u2f2(uhi[e]);
            alo0 += lo.x; alo1 += lo.y;
            ahi0 += hi.x; ahi1 += hi.y;
        }
    }
    for (; j < end; j++) {
        int sI = d_srcs[j];
        const uint32_t* xr = reinterpret_cast<const uint32_t*>(d_hwh + (size_t)sI * DIM);
        float2 lo = u2f2(xr[lane]), hi = u2f2(xr[lane + 32]);
        alo0 += lo.x; alo1 += lo.y;
        ahi0 += hi.x; ahi1 += hi.y;
    }
    int clo = lane * 2, chi = 64 + lane * 2;
    float vals[4] = {alo0 * dn, alo1 * dn, ahi0 * dn, ahi1 * dn};
    int cols[4] = {clo, clo + 1, chi, chi + 1};
    float p = 0.f;
#pragma unroll
    for (int q = 0; q < 4; q++) {
        int c = cols[q];
        float v = vals[q] + gcn_b[c];
        v = v > 0.f ? v : (__expf(v) - 1.0f);
        v = g2[c] * (v - m2[c]) * rsqrtf(v2[c] + 1e-5f) + b2[c];
        vals[q] = v;
        p += v * gateW[c];
    }
    *reinterpret_cast<float2*>(d_h2 + (size_t)n * DIM + clo) = make_float2(vals[0], vals[1]);
    *reinterpret_cast<float2*>(d_h2 + (size_t)n * DIM + chi) = make_float2(vals[2], vals[3]);
#pragma unroll
    for (int o = 16; o; o >>= 1) p += __shfl_xor_sync(0xffffffffu, p, o);
    if (lane == 0) d_gate[n] = p + gate_b[0];
}

// ---------------- pooling ----------------
__global__ __launch_bounds__(128) void k_pool(const int* __restrict__ batch) {
    __shared__ int sr[2];
    __shared__ float smax[4], ssum[4];
    int b = blockIdx.x;
    int tid = threadIdx.x, lane = tid & 31, wid = tid >> 5;
    if (tid == 0) {
        int lo = 0, hi = Nn;
        while (lo < hi) { int m = (lo + hi) >> 1; if (batch[m] < b) lo = m + 1; else hi = m; }
        sr[0] = lo;
        int lo2 = lo, hi2 = Nn;
        while (lo2 < hi2) { int m = (lo2 + hi2) >> 1; if (batch[m] < b + 1) lo2 = m + 1; else hi2 = m; }
        sr[1] = lo2;
    }
    __syncthreads();
    int lo = sr[0], hi = sr[1];
    if (lo >= hi) { d_grep[(size_t)b * DIM + tid] = 0.f; return; }
    float mv = -1e30f;
    for (int n = lo + tid; n < hi; n += 128) mv = fmaxf(mv, d_gate[n]);
#pragma unroll
    for (int o = 16; o; o >>= 1) mv = fmaxf(mv, __shfl_xor_sync(0xffffffffu, mv, o));
    if (lane == 0) smax[wid] = mv;
    __syncthreads();
    mv = fmaxf(fmaxf(smax[0], smax[1]), fmaxf(smax[2], smax[3]));
    float sv = 0.f;
    for (int n = lo + tid; n < hi; n += 128) sv += __expf(d_gate[n] - mv);
#pragma unroll
    for (int o = 16; o; o >>= 1) sv += __shfl_xor_sync(0xffffffffu, sv, o);
    if (lane == 0) ssum[wid] = sv;
    __syncthreads();
    sv = ssum[0] + ssum[1] + ssum[2] + ssum[3];
    float rcp = 1.0f / (sv + 1e-16f);
    float acc = 0.f;
    int n = lo;
    for (; n + 2 <= hi; n += 2) {
        float wA = __expf(d_gate[n] - mv) * rcp;
        float wB = __expf(d_gate[n + 1] - mv) * rcp;
        acc += wA * d_h2[(size_t)n * DIM + tid] + wB * d_h2[(size_t)(n + 1) * DIM + tid];
    }
    if (n < hi) acc += __expf(d_gate[n] - mv) * rcp * d_h2[(size_t)n * DIM + tid];
    d_grep[(size_t)b * DIM + tid] = acc;
}

// ---------------- LSTM input projection ----------------
__global__ void k_xpre(const float* __restrict__ quant, const float* __restrict__ Wih,
                       const float* __restrict__ bih, const float* __restrict__ bhh) {
    __shared__ float4 sq[32][8];
    int t = blockIdx.x;
    int bbase = blockIdx.y * 32;
    int tid = threadIdx.x;  // 512
    for (int i = tid; i < 32 * 8; i += 512) {
        int b = i >> 3, k = i & 7;
        sq[b][k] = reinterpret_cast<const float4*>(quant + ((size_t)(bbase + b) * Tt + t) * QD)[k];
    }
    __syncthreads();
    int j = tid;
    float wr[QD];
#pragma unroll
    for (int k = 0; k < QD; k++) wr[k] = Wih[j * QD + k];
    float bs = bih[j] + bhh[j];
    for (int b = 0; b < 32; b++) {
        float acc = bs;
#pragma unroll
        for (int k8 = 0; k8 < 8; k8++) {
            float4 q = sq[b][k8];
            acc += q.x * wr[k8 * 4] + q.y * wr[k8 * 4 + 1] + q.z * wr[k8 * 4 + 2] + q.w * wr[k8 * 4 + 3];
        }
        d_xpre[((size_t)(bbase + b) * Tt + t) * 512 + j] = acc;
    }
}

// ---------------- persistent LSTM ----------------
__global__ __launch_bounds__(512) void k_lstm_persist(const float* __restrict__ Whh) {
    extern __shared__ float dyn[];
    float* s_w    = dyn;
    float* s_h    = dyn + SW_FLOATS;
    float* s_gate = dyn + SW_FLOATS + SH_FLOATS;
    int j = threadIdx.x;

    float4 w4[16];
    const float4* Wr = reinterpret_cast<const float4*>(Whh + (size_t)j * 128);
#pragma unroll
    for (int q = 0; q < 16; q++) w4[q] = Wr[q];
#pragma unroll
    for (int q = 0; q < 16; q++) {
        float4 v = Wr[16 + q];
        *reinterpret_cast<float4*>(&s_w[j * 68 + q * 4]) = v;
    }
    if (j < BPC * 128) s_h[j] = 0.f;
    float c0 = 0.f, c1 = 0.f;
    __syncthreads();

    int bglob = blockIdx.x * BPC;
    const float* xp0 = d_xpre + (size_t)(bglob + 0) * Tt * 512;
    const float* xp1 = d_xpre + (size_t)(bglob + 1) * Tt * 512;

    for (int t = 0; t < Tt; t++) {
        float x0 = xp0[t * 512 + j];
        float x1 = xp1[t * 512 + j];
        float a0 = 0.f, a1 = 0.f;
#pragma unroll
        for (int q = 0; q < 16; q++) {
            float4 h0 = *reinterpret_cast<const float4*>(&s_h[0 * 128 + q * 4]);
            float4 h1 = *reinterpret_cast<const float4*>(&s_h[1 * 128 + q * 4]);
            float4 wv = w4[q];
            a0 += wv.x * h0.x + wv.y * h0.y + wv.z * h0.z + wv.w * h0.w;
            a1 += wv.x * h1.x + wv.y * h1.y + wv.z * h1.z + wv.w * h1.w;
        }
#pragma unroll
        for (int q = 0; q < 16; q++) {
            float4 wv = *reinterpret_cast<const float4*>(&s_w[j * 68 + q * 4]);
            float4 h0 = *reinterpret_cast<const float4*>(&s_h[0 * 128 + 64 + q * 4]);
            float4 h1 = *reinterpret_cast<const float4*>(&s_h[1 * 128 + 64 + q * 4]);
            a0 += wv.x * h0.x + wv.y * h0.y + wv.z * h0.z + wv.w * h0.w;
            a1 += wv.x * h1.x + wv.y * h1.y + wv.z * h1.z + wv.w * h1.w;
        }
        s_gate[0 * 512 + j] = a0 + x0;
        s_gate[1 * 512 + j] = a1 + x1;
        __syncthreads();
        if (j < 256) {
            int b = j >> 7, u = j & 127;
            float gi = s_gate[b * 512 + u];
            float gf = s_gate[b * 512 + 128 + u];
            float gg = s_gate[b * 512 + 256 + u];
            float go = s_gate[b * 512 + 384 + u];
            float cv = (j < 128) ? c0 : c1;
            cv = sigf(gf) * cv + sigf(gi) * tanhf(gg);
            if (j < 128) c0 = cv; else c1 = cv;
            s_h[b * 128 + u] = sigf(go) * tanhf(cv);
        }
        __syncthreads();
    }
    if (j < BPC * 128) {
        int b = j >> 7, u = j & 127;
        d_hT[u * Bb + (bglob + b)] = s_h[b * 128 + u];
    }
}

// ---------------- final linear ----------------
__global__ void k_final(const float* __restrict__ fcW, const float* __restrict__ fcb,
                        float* __restrict__ out) {
    int b = threadIdx.x;  // 256
    float acc = fcb[0];
#pragma unroll 4
    for (int c = 0; c < DIM; c++) acc += d_grep[b * DIM + c] * fcW[c];
#pragma unroll 4
    for (int u = 0; u < LH; u++) acc += d_hT[u * Bb + b] * fcW[DIM + u];
    out[b] = acc;
}

// ---------------- launch ----------------
extern "C" void kernel_launch(void* const* d_in, const int* in_sizes, int n_in,
                              void* d_out, int out_size) {
    (void)in_sizes; (void)n_in; (void)out_size;
    const float* x       = (const float*)d_in[0];
    const int*   ei      = (const int*)d_in[1];
    const int*   batch   = (const int*)d_in[2];
    const float* quant   = (const float*)d_in[3];
    const float* gat_W   = (const float*)d_in[4];
    const float* att_src = (const float*)d_in[5];
    const float* att_dst = (const float*)d_in[6];
    const float* gat_b   = (const float*)d_in[7];
    const float* bn1_g   = (const float*)d_in[8];
    const float* bn1_b   = (const float*)d_in[9];
    const float* bn1_m   = (const float*)d_in[10];
    const float* bn1_v   = (const float*)d_in[11];
    const float* gcn_W   = (const float*)d_in[12];
    const float* gcn_b   = (const float*)d_in[13];
    const float* bn2_g   = (const float*)d_in[14];
    const float* bn2_b   = (const float*)d_in[15];
    const float* bn2_m   = (const float*)d_in[16];
    const float* bn2_v   = (const float*)d_in[17];
    const float* gate_W  = (const float*)d_in[18];
    const float* gate_b  = (const float*)d_in[19];
    const float* Wih     = (const float*)d_in[20];
    const float* Whh     = (const float*)d_in[21];
    const float* bih     = (const float*)d_in[22];
    const float* bhh     = (const float*)d_in[23];
    const float* fcW     = (const float*)d_in[24];
    const float* fcb     = (const float*)d_in[25];
    float* out = (float*)d_out;

    static cudaStream_t s_lstm = nullptr, s_csr = nullptr;
    static cudaEvent_t evA = nullptr, evB = nullptr, evC = nullptr, evD = nullptr;
    static cudaEvent_t evE1 = nullptr, evE3 = nullptr;
    if (s_lstm == nullptr) {
        cudaStreamCreateWithFlags(&s_lstm, cudaStreamNonBlocking);
        cudaStreamCreateWithFlags(&s_csr, cudaStreamNonBlocking);
        cudaEventCreateWithFlags(&evA, cudaEventDisableTiming);
        cudaEventCreateWithFlags(&evB, cudaEventDisableTiming);
        cudaEventCreateWithFlags(&evC, cudaEventDisableTiming);
        cudaEventCreateWithFlags(&evD, cudaEventDisableTiming);
        cudaEventCreateWithFlags(&evE1, cudaEventDisableTiming);
        cudaEventCreateWithFlags(&evE3, cudaEventDisableTiming);
        cudaFuncSetAttribute(k_lstm_persist, cudaFuncAttributeMaxDynamicSharedMemorySize, LSTM_SMEM_BYTES);
        cudaFuncSetAttribute(k_lstm_persist, cudaFuncAttributePreferredSharedMemoryCarveout, 100);
    }

    // fork: LSTM branch
    cudaEventRecord(evA, 0);
    cudaStreamWaitEvent(s_lstm, evA, 0);
    k_xpre<<<dim3(Tt, Bb / 32), 512, 0, s_lstm>>>(quant, Wih, bih, bhh);
    k_lstm_persist<<<LCTAS, 512, LSTM_SMEM_BYTES, s_lstm>>>(Whh);
    cudaEventRecord(evB, s_lstm);

    // fork: CSR build + scatter overlap with gat_gemm
    cudaEventRecord(evC, 0);
    cudaStreamWaitEvent(s_csr, evC, 0);
    k_init<<<(Nn + 511) / 512, 512, 0, s_csr>>>();
    k_count<<<(NeT + 255) / 256, 256, 0, s_csr>>>(ei);
    k_scan1<<<SCAN_B, 512, 0, s_csr>>>();
    k_scan2<<<1, 32, 0, s_csr>>>();
    k_scan3<<<SCAN_B, 512, 0, s_csr>>>();
    k_scatter<<<(NeT + 255) / 256, 256, 0, s_csr>>>(ei);
    cudaEventRecord(evD, s_csr);

    // graph branch
    k_gat_gemm<<<(Nn + 63) / 64, 256>>>(x, gat_W, att_src, att_dst);
    cudaStreamWaitEvent(0, evD, 0);

    // pipelined gather3 -> gcn_gemm (two node-range halves)
    k_gather3<<<SPL / 8, 256>>>(0, SPL, gat_b, bn1_g, bn1_b, bn1_m, bn1_v);
    cudaEventRecord(evE1, 0);
    cudaStreamWaitEvent(s_csr, evE1, 0);
    k_gcn_gemm<<<SPL / 64, 256, 0, s_csr>>>(0, SPL, gcn_W);          // overlaps gather3 H2
    cudaEventRecord(evE3, s_csr);
    k_gather3<<<(Nn - SPL + 7) / 8, 256>>>(SPL, Nn - SPL, gat_b, bn1_g, bn1_b, bn1_m, bn1_v);
    k_gcn_gemm<<<(Nn - SPL + 63) / 64, 256>>>(SPL, Nn - SPL, gcn_W);
    cudaStreamWaitEvent(0, evE3, 0);

    k_gather4<<<(Nn + 7) / 8, 256>>>(gcn_b, bn2_g, bn2_b, bn2_m, bn2_v, gate_W, gate_b);
    k_pool<<<Bb, 128>>>(batch);

    // join
    cudaStreamWaitEvent(0, evB, 0);
    k_final<<<1, 256>>>(fcW, fcb, out);
}